// round 1
// baseline (speedup 1.0000x reference)
#include <cuda_runtime.h>

#define BB   128
#define LL   131072
#define TT   4096
#define HIST 64
#define WIN  32
#define DIMS 32
#define NP   16

// Scratch (no allocations allowed). scores padded for scan prefetch overrun.
__device__ float  g_scores[(size_t)BB * TT * NP + 1024];
__device__ float2 g_params[(size_t)BB * TT];

__device__ __forceinline__ float ex2f(float x) {
    float r; asm("ex2.approx.f32 %0, %1;" : "=f"(r) : "f"(x)); return r;
}
__device__ __forceinline__ float rcpf(float x) {
    float r; asm("rcp.approx.f32 %0, %1;" : "=f"(r) : "f"(x)); return r;
}

// ---------------------------------------------------------------------------
// Kernel A: conv (64-tap, stride 32) + relu + key projection + clip + log2e
// Block: 128 threads, covers one b and 256 t's (2 t per thread, shared w-LDS).
// Bank-conflict-free via per-thread rotation of the tap index.
// ---------------------------------------------------------------------------
#define TTA 256
__global__ void __launch_bounds__(128)
conv_scores_kernel(const float* __restrict__ x,
                   const float* __restrict__ conv_w,
                   const float* __restrict__ conv_b,
                   const float* __restrict__ keys)
{
    __shared__ float sx[TTA * WIN + HIST];   // 8256 floats
    __shared__ float sw[DIMS * HIST];        // 2048 floats, [d][h]
    __shared__ float sk[DIMS * NP];          // 512 floats, [d][p]
    __shared__ float sb[DIMS];

    const int b = blockIdx.y;
    const int tile = blockIdx.x;
    const int tid = threadIdx.x;

    const long base = (long)tile * TTA * WIN - (HIST - 1);
    const float* xb = x + (size_t)b * LL;

    for (int i = tid; i < TTA * WIN + HIST; i += 128) {
        long g = base + i;
        sx[i] = (g >= 0 && g < LL) ? xb[g] : 0.f;
    }
    for (int i = tid; i < DIMS * HIST; i += 128) sw[i] = conv_w[i];
    for (int i = tid; i < DIMS * NP; i += 128)   sk[i] = keys[i];
    if (tid < DIMS) sb[tid] = conv_b[tid];
    __syncthreads();

    float acca[DIMS], accb[DIMS];
#pragma unroll
    for (int d = 0; d < DIMS; d++) { acca[d] = 0.f; accb[d] = 0.f; }

    const int ta = tid;          // local t in [0,128)
    const int tb = tid + 128;    // local t in [128,256)

    for (int h = 0; h < HIST; h++) {
        const int hp = (h + tid) & 63;              // rotation: conflict-free banks
        const float xa = sx[ta * WIN + hp];
        const float xv = sx[tb * WIN + hp];
#pragma unroll
        for (int d = 0; d < DIMS; d++) {
            const float wv = sw[d * HIST + hp];
            acca[d] = fmaf(xa, wv, acca[d]);
            accb[d] = fmaf(xv, wv, accb[d]);
        }
    }

    const float L2E = 1.4426950408889634f;
#pragma unroll
    for (int s = 0; s < 2; s++) {
        const int gt = tile * TTA + tid + s * 128;
        float sc[NP];
#pragma unroll
        for (int p = 0; p < NP; p++) sc[p] = 0.f;
#pragma unroll
        for (int d = 0; d < DIMS; d++) {
            const float vd = fmaxf((s == 0 ? acca[d] : accb[d]) + sb[d], 0.f);
#pragma unroll
            for (int p = 0; p < NP; p++)
                sc[p] = fmaf(vd, sk[d * NP + p], sc[p]);
        }
        float4* dst = (float4*)(g_scores + ((size_t)b * TT + gt) * NP);
#pragma unroll
        for (int q = 0; q < 4; q++) {
            float4 v;
            v.x = fminf(fmaxf(sc[q * 4 + 0], 0.f), 6.f) * L2E;
            v.y = fminf(fmaxf(sc[q * 4 + 1], 0.f), 6.f) * L2E;
            v.z = fminf(fmaxf(sc[q * 4 + 2], 0.f), 6.f) * L2E;
            v.w = fminf(fmaxf(sc[q * 4 + 3], 0.f), 6.f) * L2E;
            dst[q] = v;
        }
    }
}

// ---------------------------------------------------------------------------
// Kernel B: sequential softmax scan. 4 lanes per b (4 patterns/lane),
// 8 b per warp, 16 warps total. Latency-optimized dependency chain:
//   p -> z=FFMA -> EX2 x4 -> pair tree -> 2x shfl -> RCP -> p   (~132 cyc)
// A-update and next-step w precomputation are off the critical chain.
// ---------------------------------------------------------------------------
__global__ void __launch_bounds__(32)
scan_kernel(const float* __restrict__ avg0, const float* __restrict__ shapes)
{
    const int lane = threadIdx.x;
    const int grp  = lane >> 2;
    const int j    = lane & 3;
    const int b    = blockIdx.x * 8 + grp;

    const float L2E = 1.4426950408889634f;
    const float C16 = L2E * (1.f / 16.f);

    // A stored in log2 units, with +C16 so the uniform init formula for w holds.
    float A0 = avg0[b * NP + j * 4 + 0] * L2E + C16;
    float A1 = avg0[b * NP + j * 4 + 1] * L2E + C16;
    float A2 = avg0[b * NP + j * 4 + 2] * L2E + C16;
    float A3 = avg0[b * NP + j * 4 + 3] * L2E + C16;

    const float s00 = shapes[(j * 4 + 0) * 2 + 0], s10 = shapes[(j * 4 + 0) * 2 + 1];
    const float s01 = shapes[(j * 4 + 1) * 2 + 0], s11 = shapes[(j * 4 + 1) * 2 + 1];
    const float s02 = shapes[(j * 4 + 2) * 2 + 0], s12 = shapes[(j * 4 + 2) * 2 + 1];
    const float s03 = shapes[(j * 4 + 3) * 2 + 0], s13 = shapes[(j * 4 + 3) * 2 + 1];

    const float4* sp = (const float4*)(g_scores + (size_t)b * TT * NP);
    float2* prm = g_params + (size_t)b * TT;

    float4 q0 = sp[0 * 4 + j];
    float4 q1 = sp[1 * 4 + j];
    float4 q2 = sp[2 * 4 + j];
    float4 q3 = sp[3 * 4 + j];

    float pp0 = 0.f, pp1 = 0.f, pp2 = 0.f, pp3 = 0.f;
    float w0 = (q0.x + C16) - A0;
    float w1 = (q0.y + C16) - A1;
    float w2 = (q0.z + C16) - A2;
    float w3 = (q0.w + C16) - A3;

#define STEP(tt, QN)                                                          \
    {                                                                         \
        float z0 = fmaf(pp0, -L2E, w0);                                       \
        float z1 = fmaf(pp1, -L2E, w1);                                       \
        float z2 = fmaf(pp2, -L2E, w2);                                       \
        float z3 = fmaf(pp3, -L2E, w3);                                       \
        float e0 = ex2f(z0), e1 = ex2f(z1), e2 = ex2f(z2), e3 = ex2f(z3);     \
        float An0 = fmaf(pp0, L2E, A0) - C16;                                 \
        float An1 = fmaf(pp1, L2E, A1) - C16;                                 \
        float An2 = fmaf(pp2, L2E, A2) - C16;                                 \
        float An3 = fmaf(pp3, L2E, A3) - C16;                                 \
        float ss = (e0 + e1) + (e2 + e3);                                     \
        ss += __shfl_xor_sync(0xffffffffu, ss, 1, 4);                         \
        ss += __shfl_xor_sync(0xffffffffu, ss, 2, 4);                         \
        float r = rcpf(ss);                                                   \
        float u0 = fmaf(e0, s00, fmaf(e1, s01, fmaf(e2, s02, e3 * s03)));     \
        float u1 = fmaf(e0, s10, fmaf(e1, s11, fmaf(e2, s12, e3 * s13)));     \
        u0 += __shfl_xor_sync(0xffffffffu, u0, 1, 4);                         \
        u0 += __shfl_xor_sync(0xffffffffu, u0, 2, 4);                         \
        u1 += __shfl_xor_sync(0xffffffffu, u1, 1, 4);                         \
        u1 += __shfl_xor_sync(0xffffffffu, u1, 2, 4);                         \
        pp0 = e0 * r; pp1 = e1 * r; pp2 = e2 * r; pp3 = e3 * r;               \
        w0 = ((QN).x + C16) - An0;                                            \
        w1 = ((QN).y + C16) - An1;                                            \
        w2 = ((QN).z + C16) - An2;                                            \
        w3 = ((QN).w + C16) - An3;                                            \
        A0 = An0; A1 = An1; A2 = An2; A3 = An3;                               \
        if (j == 0) prm[tt] = make_float2(u0 * r, u1 * r);                    \
    }

    for (int t = 0; t < TT; t += 4) {
        float4 n0 = sp[(t + 4) * 4 + j];
        STEP(t + 0, q1);
        float4 n1 = sp[(t + 5) * 4 + j];
        STEP(t + 1, q2);
        float4 n2 = sp[(t + 6) * 4 + j];
        STEP(t + 2, q3);
        float4 n3 = sp[(t + 7) * 4 + j];
        STEP(t + 3, n0);
        q0 = n0; q1 = n1; q2 = n2; q3 = n3;
    }
#undef STEP
}

// ---------------------------------------------------------------------------
// Kernel C: epilogue — out = relu(offset + noise*std - x), memory-bound
// ---------------------------------------------------------------------------
__global__ void __launch_bounds__(256)
epilogue_kernel(const float* __restrict__ x,
                const float* __restrict__ noise,
                float* __restrict__ out)
{
    const int b  = blockIdx.y;
    const int l4 = blockIdx.x * 256 + threadIdx.x;   // float4 index within row
    const int t  = (l4 * 4) >> 5;

    const float2 pr = g_params[(size_t)b * TT + t];
    const float4 xv = ((const float4*)(x     + (size_t)b * LL))[l4];
    const float4 nv = ((const float4*)(noise + (size_t)b * LL))[l4];

    float4 o;
    o.x = fmaxf(fmaf(nv.x, pr.y, pr.x) - xv.x, 0.f);
    o.y = fmaxf(fmaf(nv.y, pr.y, pr.x) - xv.y, 0.f);
    o.z = fmaxf(fmaf(nv.z, pr.y, pr.x) - xv.z, 0.f);
    o.w = fmaxf(fmaf(nv.w, pr.y, pr.x) - xv.w, 0.f);
    ((float4*)out)[(size_t)b * (LL / 4) + l4] = o;
}

// ---------------------------------------------------------------------------
extern "C" void kernel_launch(void* const* d_in, const int* in_sizes, int n_in,
                              void* d_out, int out_size)
{
    const float* x      = (const float*)d_in[0];
    const float* avg    = (const float*)d_in[1];
    const float* noise  = (const float*)d_in[2];
    const float* conv_w = (const float*)d_in[3];
    const float* conv_b = (const float*)d_in[4];
    const float* keys   = (const float*)d_in[5];
    const float* shapes = (const float*)d_in[6];
    float* out = (float*)d_out;

    conv_scores_kernel<<<dim3(TT / TTA, BB), 128>>>(x, conv_w, conv_b, keys);
    scan_kernel<<<BB / 8, 32>>>(avg, shapes);
    epilogue_kernel<<<dim3(LL / 1024, BB), 256>>>(x, noise, out);
}

// round 2
// speedup vs baseline: 2.7572x; 2.7572x over previous
#include <cuda_runtime.h>

#define BB   128
#define LL   131072
#define TT   4096
#define HIST 64
#define WIN  32
#define DIMS 32
#define NP   16

#define SEGC   256      // output steps per segment
#define SEGW   512      // warmup steps
#define NSEG   (TT / SEGC)   // 16

// Scratch (no allocations allowed). scores padded for scan prefetch overrun.
__device__ float  g_scores[(size_t)BB * TT * NP + 1024];
__device__ float2 g_params[(size_t)BB * TT];

__device__ __forceinline__ float ex2f(float x) {
    float r; asm("ex2.approx.f32 %0, %1;" : "=f"(r) : "f"(x)); return r;
}
__device__ __forceinline__ float rcpf(float x) {
    float r; asm("rcp.approx.f32 %0, %1;" : "=f"(r) : "f"(x)); return r;
}

// ---------------------------------------------------------------------------
// Kernel A: conv (64-tap, stride 32) + relu + key projection + clip + log2e
// ---------------------------------------------------------------------------
#define TTA 256
__global__ void __launch_bounds__(128)
conv_scores_kernel(const float* __restrict__ x,
                   const float* __restrict__ conv_w,
                   const float* __restrict__ conv_b,
                   const float* __restrict__ keys)
{
    __shared__ float sx[TTA * WIN + HIST];
    __shared__ float sw[DIMS * HIST];
    __shared__ float sk[DIMS * NP];
    __shared__ float sb[DIMS];

    const int b = blockIdx.y;
    const int tile = blockIdx.x;
    const int tid = threadIdx.x;

    const long base = (long)tile * TTA * WIN - (HIST - 1);
    const float* xb = x + (size_t)b * LL;

    for (int i = tid; i < TTA * WIN + HIST; i += 128) {
        long g = base + i;
        sx[i] = (g >= 0 && g < LL) ? xb[g] : 0.f;
    }
    for (int i = tid; i < DIMS * HIST; i += 128) sw[i] = conv_w[i];
    for (int i = tid; i < DIMS * NP; i += 128)   sk[i] = keys[i];
    if (tid < DIMS) sb[tid] = conv_b[tid];
    __syncthreads();

    float acca[DIMS], accb[DIMS];
#pragma unroll
    for (int d = 0; d < DIMS; d++) { acca[d] = 0.f; accb[d] = 0.f; }

    const int ta = tid;
    const int tb = tid + 128;

    for (int h = 0; h < HIST; h++) {
        const int hp = (h + tid) & 63;
        const float xa = sx[ta * WIN + hp];
        const float xv = sx[tb * WIN + hp];
#pragma unroll
        for (int d = 0; d < DIMS; d++) {
            const float wv = sw[d * HIST + hp];
            acca[d] = fmaf(xa, wv, acca[d]);
            accb[d] = fmaf(xv, wv, accb[d]);
        }
    }

    const float L2E = 1.4426950408889634f;
#pragma unroll
    for (int s = 0; s < 2; s++) {
        const int gt = tile * TTA + tid + s * 128;
        float sc[NP];
#pragma unroll
        for (int p = 0; p < NP; p++) sc[p] = 0.f;
#pragma unroll
        for (int d = 0; d < DIMS; d++) {
            const float vd = fmaxf((s == 0 ? acca[d] : accb[d]) + sb[d], 0.f);
#pragma unroll
            for (int p = 0; p < NP; p++)
                sc[p] = fmaf(vd, sk[d * NP + p], sc[p]);
        }
        float4* dst = (float4*)(g_scores + ((size_t)b * TT + gt) * NP);
#pragma unroll
        for (int q = 0; q < 4; q++) {
            float4 v;
            v.x = fminf(fmaxf(sc[q * 4 + 0], 0.f), 6.f) * L2E;
            v.y = fminf(fmaxf(sc[q * 4 + 1], 0.f), 6.f) * L2E;
            v.z = fminf(fmaxf(sc[q * 4 + 2], 0.f), 6.f) * L2E;
            v.w = fminf(fmaxf(sc[q * 4 + 3], 0.f), 6.f) * L2E;
            dst[q] = v;
        }
    }
}

// ---------------------------------------------------------------------------
// Kernel B: chunked softmax scan with contraction warmup.
// 2048 chains = 128 batches x 16 segments; 8 chains/warp (4 lanes each);
// 256 warps (grid 256 -> escapes the low-grid throttle regime).
// Segment k outputs t in [k*256, (k+1)*256), warming up from
// t0 = max(0, k*256 - 512) with approximate init A = avg0 (exact for k<=2;
// the recurrence's negative feedback contracts init error below 1e-4
// within 512 steps). Warmup steps skip all u/store work.
// ---------------------------------------------------------------------------
__global__ void __launch_bounds__(32)
scan_kernel(const float* __restrict__ avg0, const float* __restrict__ shapes)
{
    const int lane = threadIdx.x;
    const int grp  = lane >> 2;
    const int j    = lane & 3;
    const int seg  = blockIdx.x >> 4;
    const int b    = (blockIdx.x & 15) * 8 + grp;

    const int s_start = seg * SEGC;
    const int t0 = (s_start - SEGW > 0) ? (s_start - SEGW) : 0;

    const float L2E = 1.4426950408889634f;
    const float C16 = L2E * (1.f / 16.f);

    float A0 = avg0[b * NP + j * 4 + 0] * L2E + C16;
    float A1 = avg0[b * NP + j * 4 + 1] * L2E + C16;
    float A2 = avg0[b * NP + j * 4 + 2] * L2E + C16;
    float A3 = avg0[b * NP + j * 4 + 3] * L2E + C16;

    const float s00 = shapes[(j * 4 + 0) * 2 + 0], s10 = shapes[(j * 4 + 0) * 2 + 1];
    const float s01 = shapes[(j * 4 + 1) * 2 + 0], s11 = shapes[(j * 4 + 1) * 2 + 1];
    const float s02 = shapes[(j * 4 + 2) * 2 + 0], s12 = shapes[(j * 4 + 2) * 2 + 1];
    const float s03 = shapes[(j * 4 + 3) * 2 + 0], s13 = shapes[(j * 4 + 3) * 2 + 1];

    const float4* sp = (const float4*)(g_scores + (size_t)b * TT * NP);
    float2* prm = g_params + (size_t)b * TT;

    float4 q0 = sp[(t0 + 0) * 4 + j];
    float4 q1 = sp[(t0 + 1) * 4 + j];
    float4 q2 = sp[(t0 + 2) * 4 + j];
    float4 q3 = sp[(t0 + 3) * 4 + j];

    float pp0 = 0.f, pp1 = 0.f, pp2 = 0.f, pp3 = 0.f;
    float w0 = (q0.x + C16) - A0;
    float w1 = (q0.y + C16) - A1;
    float w2 = (q0.z + C16) - A2;
    float w3 = (q0.w + C16) - A3;

// Shared chain core: z -> e -> sum -> shfl -> rcp -> pp; A/w updates off-chain.
#define CHAIN(QN)                                                             \
        float z0 = fmaf(pp0, -L2E, w0);                                       \
        float z1 = fmaf(pp1, -L2E, w1);                                       \
        float z2 = fmaf(pp2, -L2E, w2);                                       \
        float z3 = fmaf(pp3, -L2E, w3);                                       \
        float e0 = ex2f(z0), e1 = ex2f(z1), e2 = ex2f(z2), e3 = ex2f(z3);     \
        float An0 = fmaf(pp0, L2E, A0) - C16;                                 \
        float An1 = fmaf(pp1, L2E, A1) - C16;                                 \
        float An2 = fmaf(pp2, L2E, A2) - C16;                                 \
        float An3 = fmaf(pp3, L2E, A3) - C16;                                 \
        float ss = (e0 + e1) + (e2 + e3);                                     \
        ss += __shfl_xor_sync(0xffffffffu, ss, 1, 4);                         \
        ss += __shfl_xor_sync(0xffffffffu, ss, 2, 4);                         \
        float r = rcpf(ss);                                                   \
        pp0 = e0 * r; pp1 = e1 * r; pp2 = e2 * r; pp3 = e3 * r;               \
        w0 = ((QN).x + C16) - An0;                                            \
        w1 = ((QN).y + C16) - An1;                                            \
        w2 = ((QN).z + C16) - An2;                                            \
        w3 = ((QN).w + C16) - An3;                                            \
        A0 = An0; A1 = An1; A2 = An2; A3 = An3;

#define STEPW(QN) { CHAIN(QN) }

#define STEP(tt, QN)                                                          \
    {                                                                         \
        CHAIN(QN)                                                             \
        float u0 = fmaf(e0, s00, fmaf(e1, s01, fmaf(e2, s02, e3 * s03)));     \
        float u1 = fmaf(e0, s10, fmaf(e1, s11, fmaf(e2, s12, e3 * s13)));     \
        u0 += __shfl_xor_sync(0xffffffffu, u0, 1, 4);                         \
        u0 += __shfl_xor_sync(0xffffffffu, u0, 2, 4);                         \
        u1 += __shfl_xor_sync(0xffffffffu, u1, 1, 4);                         \
        u1 += __shfl_xor_sync(0xffffffffu, u1, 2, 4);                         \
        if (j == 0) prm[tt] = make_float2(u0 * r, u1 * r);                    \
    }

    int t = t0;
    // Warmup: no outputs
    for (; t < s_start; t += 4) {
        float4 n0 = sp[(t + 4) * 4 + j];
        STEPW(q1);
        float4 n1 = sp[(t + 5) * 4 + j];
        STEPW(q2);
        float4 n2 = sp[(t + 6) * 4 + j];
        STEPW(q3);
        float4 n3 = sp[(t + 7) * 4 + j];
        STEPW(n0);
        q0 = n0; q1 = n1; q2 = n2; q3 = n3;
    }
    // Main: emit params for this segment
    const int s_end = s_start + SEGC;
    for (; t < s_end; t += 4) {
        float4 n0 = sp[(t + 4) * 4 + j];
        STEP(t + 0, q1);
        float4 n1 = sp[(t + 5) * 4 + j];
        STEP(t + 1, q2);
        float4 n2 = sp[(t + 6) * 4 + j];
        STEP(t + 2, q3);
        float4 n3 = sp[(t + 7) * 4 + j];
        STEP(t + 3, n0);
        q0 = n0; q1 = n1; q2 = n2; q3 = n3;
    }
#undef STEP
#undef STEPW
#undef CHAIN
}

// ---------------------------------------------------------------------------
// Kernel C: epilogue — out = relu(offset + noise*std - x), memory-bound
// ---------------------------------------------------------------------------
__global__ void __launch_bounds__(256)
epilogue_kernel(const float* __restrict__ x,
                const float* __restrict__ noise,
                float* __restrict__ out)
{
    const int b  = blockIdx.y;
    const int l4 = blockIdx.x * 256 + threadIdx.x;
    const int t  = (l4 * 4) >> 5;

    const float2 pr = g_params[(size_t)b * TT + t];
    const float4 xv = ((const float4*)(x     + (size_t)b * LL))[l4];
    const float4 nv = ((const float4*)(noise + (size_t)b * LL))[l4];

    float4 o;
    o.x = fmaxf(fmaf(nv.x, pr.y, pr.x) - xv.x, 0.f);
    o.y = fmaxf(fmaf(nv.y, pr.y, pr.x) - xv.y, 0.f);
    o.z = fmaxf(fmaf(nv.z, pr.y, pr.x) - xv.z, 0.f);
    o.w = fmaxf(fmaf(nv.w, pr.y, pr.x) - xv.w, 0.f);
    ((float4*)out)[(size_t)b * (LL / 4) + l4] = o;
}

// ---------------------------------------------------------------------------
extern "C" void kernel_launch(void* const* d_in, const int* in_sizes, int n_in,
                              void* d_out, int out_size)
{
    const float* x      = (const float*)d_in[0];
    const float* avg    = (const float*)d_in[1];
    const float* noise  = (const float*)d_in[2];
    const float* conv_w = (const float*)d_in[3];
    const float* conv_b = (const float*)d_in[4];
    const float* keys   = (const float*)d_in[5];
    const float* shapes = (const float*)d_in[6];
    float* out = (float*)d_out;

    conv_scores_kernel<<<dim3(TT / TTA, BB), 128>>>(x, conv_w, conv_b, keys);
    scan_kernel<<<NSEG * 16, 32>>>(avg, shapes);
    epilogue_kernel<<<dim3(LL / 1024, BB), 256>>>(x, noise, out);
}

// round 3
// speedup vs baseline: 3.7801x; 1.3710x over previous
#include <cuda_runtime.h>

#define BB   128
#define LL   131072
#define TT   4096
#define HIST 64
#define WIN  32
#define DIMS 32
#define NP   16

#define SEGC   128            // output steps per segment
#define SEGW   256            // warmup steps
#define NSEG   (TT / SEGC)    // 32

// Scratch (no allocations allowed). scores padded for scan prefetch overrun.
__device__ float  g_scores[(size_t)BB * TT * NP + 1024];
// per-lane partials: [b][t][j] -> (v0, v1), j = lane quadrant (4 per chain)
__device__ float2 g_params[(size_t)BB * TT * 4];

__device__ __forceinline__ float ex2f(float x) {
    float r; asm("ex2.approx.f32 %0, %1;" : "=f"(r) : "f"(x)); return r;
}
__device__ __forceinline__ float rcpf(float x) {
    float r; asm("rcp.approx.f32 %0, %1;" : "=f"(r) : "f"(x)); return r;
}

// ---------------------------------------------------------------------------
// Kernel A: conv (64-tap, stride 32) + relu + key projection + clip + log2e
// ---------------------------------------------------------------------------
#define TTA 256
__global__ void __launch_bounds__(128)
conv_scores_kernel(const float* __restrict__ x,
                   const float* __restrict__ conv_w,
                   const float* __restrict__ conv_b,
                   const float* __restrict__ keys)
{
    __shared__ float sx[TTA * WIN + HIST];
    __shared__ float sw[DIMS * HIST];
    __shared__ float sk[DIMS * NP];
    __shared__ float sb[DIMS];

    const int b = blockIdx.y;
    const int tile = blockIdx.x;
    const int tid = threadIdx.x;

    const long base = (long)tile * TTA * WIN - (HIST - 1);
    const float* xb = x + (size_t)b * LL;

    for (int i = tid; i < TTA * WIN + HIST; i += 128) {
        long g = base + i;
        sx[i] = (g >= 0 && g < LL) ? xb[g] : 0.f;
    }
    for (int i = tid; i < DIMS * HIST; i += 128) sw[i] = conv_w[i];
    for (int i = tid; i < DIMS * NP; i += 128)   sk[i] = keys[i];
    if (tid < DIMS) sb[tid] = conv_b[tid];
    __syncthreads();

    float acca[DIMS], accb[DIMS];
#pragma unroll
    for (int d = 0; d < DIMS; d++) { acca[d] = 0.f; accb[d] = 0.f; }

    const int ta = tid;
    const int tb = tid + 128;

    for (int h = 0; h < HIST; h++) {
        const int hp = (h + tid) & 63;
        const float xa = sx[ta * WIN + hp];
        const float xv = sx[tb * WIN + hp];
#pragma unroll
        for (int d = 0; d < DIMS; d++) {
            const float wv = sw[d * HIST + hp];
            acca[d] = fmaf(xa, wv, acca[d]);
            accb[d] = fmaf(xv, wv, accb[d]);
        }
    }

    const float L2E = 1.4426950408889634f;
#pragma unroll
    for (int s = 0; s < 2; s++) {
        const int gt = tile * TTA + tid + s * 128;
        float sc[NP];
#pragma unroll
        for (int p = 0; p < NP; p++) sc[p] = 0.f;
#pragma unroll
        for (int d = 0; d < DIMS; d++) {
            const float vd = fmaxf((s == 0 ? acca[d] : accb[d]) + sb[d], 0.f);
#pragma unroll
            for (int p = 0; p < NP; p++)
                sc[p] = fmaf(vd, sk[d * NP + p], sc[p]);
        }
        float4* dst = (float4*)(g_scores + ((size_t)b * TT + gt) * NP);
#pragma unroll
        for (int q = 0; q < 4; q++) {
            float4 v;
            v.x = fminf(fmaxf(sc[q * 4 + 0], 0.f), 6.f) * L2E;
            v.y = fminf(fmaxf(sc[q * 4 + 1], 0.f), 6.f) * L2E;
            v.z = fminf(fmaxf(sc[q * 4 + 2], 0.f), 6.f) * L2E;
            v.w = fminf(fmaxf(sc[q * 4 + 3], 0.f), 6.f) * L2E;
            dst[q] = v;
        }
    }
}

// ---------------------------------------------------------------------------
// Kernel B: chunked softmax scan with contraction warmup.
// 4096 chains = 128 b x 32 segs; 8 chains/warp (4 lanes each); 512 warps.
// Depth per chain = 256 warmup + 128 output steps (segs 0-2 exact).
// Main steps store per-lane partials (no shfl reduction, no divergence
// on the in-order issue path); the epilogue sums the 4 partials.
// ---------------------------------------------------------------------------
__global__ void __launch_bounds__(32)
scan_kernel(const float* __restrict__ avg0, const float* __restrict__ shapes)
{
    const int lane = threadIdx.x;
    const int grp  = lane >> 2;
    const int j    = lane & 3;
    const int seg  = blockIdx.x >> 4;
    const int b    = (blockIdx.x & 15) * 8 + grp;

    const int s_start = seg * SEGC;
    const int t0 = (s_start - SEGW > 0) ? (s_start - SEGW) : 0;

    const float L2E = 1.4426950408889634f;
    const float C16 = L2E * (1.f / 16.f);

    float A0 = avg0[b * NP + j * 4 + 0] * L2E + C16;
    float A1 = avg0[b * NP + j * 4 + 1] * L2E + C16;
    float A2 = avg0[b * NP + j * 4 + 2] * L2E + C16;
    float A3 = avg0[b * NP + j * 4 + 3] * L2E + C16;

    const float s00 = shapes[(j * 4 + 0) * 2 + 0], s10 = shapes[(j * 4 + 0) * 2 + 1];
    const float s01 = shapes[(j * 4 + 1) * 2 + 0], s11 = shapes[(j * 4 + 1) * 2 + 1];
    const float s02 = shapes[(j * 4 + 2) * 2 + 0], s12 = shapes[(j * 4 + 2) * 2 + 1];
    const float s03 = shapes[(j * 4 + 3) * 2 + 0], s13 = shapes[(j * 4 + 3) * 2 + 1];

    const float4* sp = (const float4*)(g_scores + (size_t)b * TT * NP);
    float2* prm = g_params + (size_t)b * TT * 4;

    float4 q0 = sp[(t0 + 0) * 4 + j];
    float4 q1 = sp[(t0 + 1) * 4 + j];
    float4 q2 = sp[(t0 + 2) * 4 + j];
    float4 q3 = sp[(t0 + 3) * 4 + j];

    float pp0 = 0.f, pp1 = 0.f, pp2 = 0.f, pp3 = 0.f;
    float w0 = (q0.x + C16) - A0;
    float w1 = (q0.y + C16) - A1;
    float w2 = (q0.z + C16) - A2;
    float w3 = (q0.w + C16) - A3;

// Chain core: z -> e -> sum -> 2x shfl -> rcp -> pp; A/w updates off-chain.
#define CHAIN(QN)                                                             \
        float z0 = fmaf(pp0, -L2E, w0);                                       \
        float z1 = fmaf(pp1, -L2E, w1);                                       \
        float z2 = fmaf(pp2, -L2E, w2);                                       \
        float z3 = fmaf(pp3, -L2E, w3);                                       \
        float e0 = ex2f(z0), e1 = ex2f(z1), e2 = ex2f(z2), e3 = ex2f(z3);     \
        float An0 = fmaf(pp0, L2E, A0) - C16;                                 \
        float An1 = fmaf(pp1, L2E, A1) - C16;                                 \
        float An2 = fmaf(pp2, L2E, A2) - C16;                                 \
        float An3 = fmaf(pp3, L2E, A3) - C16;                                 \
        float ss = (e0 + e1) + (e2 + e3);                                     \
        ss += __shfl_xor_sync(0xffffffffu, ss, 1, 4);                         \
        ss += __shfl_xor_sync(0xffffffffu, ss, 2, 4);                         \
        float r = rcpf(ss);                                                   \
        pp0 = e0 * r; pp1 = e1 * r; pp2 = e2 * r; pp3 = e3 * r;               \
        w0 = ((QN).x + C16) - An0;                                            \
        w1 = ((QN).y + C16) - An1;                                            \
        w2 = ((QN).z + C16) - An2;                                            \
        w3 = ((QN).w + C16) - An3;                                            \
        A0 = An0; A1 = An1; A2 = An2; A3 = An3;

#define STEPW(QN) { CHAIN(QN) }

// Main step: per-lane partial of (u0,u1) scaled by r; no cross-lane work.
#define STEP(tt, QN)                                                          \
    {                                                                         \
        CHAIN(QN)                                                             \
        float v0 = fmaf(e0, s00, fmaf(e1, s01, fmaf(e2, s02, e3 * s03)));     \
        float v1 = fmaf(e0, s10, fmaf(e1, s11, fmaf(e2, s12, e3 * s13)));     \
        prm[(tt) * 4 + j] = make_float2(v0 * r, v1 * r);                      \
    }

    int t = t0;
    for (; t < s_start; t += 4) {
        float4 n0 = sp[(t + 4) * 4 + j];
        STEPW(q1);
        float4 n1 = sp[(t + 5) * 4 + j];
        STEPW(q2);
        float4 n2 = sp[(t + 6) * 4 + j];
        STEPW(q3);
        float4 n3 = sp[(t + 7) * 4 + j];
        STEPW(n0);
        q0 = n0; q1 = n1; q2 = n2; q3 = n3;
    }
    const int s_end = s_start + SEGC;
    for (; t < s_end; t += 4) {
        float4 n0 = sp[(t + 4) * 4 + j];
        STEP(t + 0, q1);
        float4 n1 = sp[(t + 5) * 4 + j];
        STEP(t + 1, q2);
        float4 n2 = sp[(t + 6) * 4 + j];
        STEP(t + 2, q3);
        float4 n3 = sp[(t + 7) * 4 + j];
        STEP(t + 3, n0);
        q0 = n0; q1 = n1; q2 = n2; q3 = n3;
    }
#undef STEP
#undef STEPW
#undef CHAIN
}

// ---------------------------------------------------------------------------
// Kernel C: epilogue — sums the 4 per-lane partials, then
// out = relu(offset + noise*std - x). Memory-bound.
// ---------------------------------------------------------------------------
__global__ void __launch_bounds__(256)
epilogue_kernel(const float* __restrict__ x,
                const float* __restrict__ noise,
                float* __restrict__ out)
{
    const int b  = blockIdx.y;
    const int l4 = blockIdx.x * 256 + threadIdx.x;
    const int t  = (l4 * 4) >> 5;

    const float4* pq = (const float4*)(g_params + ((size_t)b * TT + t) * 4);
    const float4 pa = pq[0];   // (v0_j0, v1_j0, v0_j1, v1_j1)
    const float4 pb = pq[1];   // (v0_j2, v1_j2, v0_j3, v1_j3)
    const float offs = (pa.x + pa.z) + (pb.x + pb.z);
    const float stdv = (pa.y + pa.w) + (pb.y + pb.w);

    const float4 xv = ((const float4*)(x     + (size_t)b * LL))[l4];
    const float4 nv = ((const float4*)(noise + (size_t)b * LL))[l4];

    float4 o;
    o.x = fmaxf(fmaf(nv.x, stdv, offs) - xv.x, 0.f);
    o.y = fmaxf(fmaf(nv.y, stdv, offs) - xv.y, 0.f);
    o.z = fmaxf(fmaf(nv.z, stdv, offs) - xv.z, 0.f);
    o.w = fmaxf(fmaf(nv.w, stdv, offs) - xv.w, 0.f);
    ((float4*)out)[(size_t)b * (LL / 4) + l4] = o;
}

// ---------------------------------------------------------------------------
extern "C" void kernel_launch(void* const* d_in, const int* in_sizes, int n_in,
                              void* d_out, int out_size)
{
    const float* x      = (const float*)d_in[0];
    const float* avg    = (const float*)d_in[1];
    const float* noise  = (const float*)d_in[2];
    const float* conv_w = (const float*)d_in[3];
    const float* conv_b = (const float*)d_in[4];
    const float* keys   = (const float*)d_in[5];
    const float* shapes = (const float*)d_in[6];
    float* out = (float*)d_out;

    conv_scores_kernel<<<dim3(TT / TTA, BB), 128>>>(x, conv_w, conv_b, keys);
    scan_kernel<<<NSEG * 16, 32>>>(avg, shapes);
    epilogue_kernel<<<dim3(LL / 1024, BB), 256>>>(x, noise, out);
}

// round 4
// speedup vs baseline: 4.4712x; 1.1828x over previous
#include <cuda_runtime.h>

#define BB   128
#define LL   131072
#define TT   4096
#define HIST 64
#define WIN  32
#define DIMS 32
#define NP   16

#define SEGC   64             // output steps per segment
#define SEGW   256            // warmup steps (proven float-exact)
#define NSEG   (TT / SEGC)    // 64

// Scores laid out [t][b][16] for coalesced scan reads. Padded for the
// prefetch overrun (up to t = TT+3, all b).
__device__ float  g_scores[(size_t)TT * BB * NP + 16384];
// params laid out [t][b]
__device__ float2 g_params[(size_t)TT * BB];

__device__ __forceinline__ float ex2f(float x) {
    float r; asm("ex2.approx.f32 %0, %1;" : "=f"(r) : "f"(x)); return r;
}
__device__ __forceinline__ float rcpf(float x) {
    float r; asm("rcp.approx.f32 %0, %1;" : "=f"(r) : "f"(x)); return r;
}

// ---------------------------------------------------------------------------
// Kernel A: conv (64-tap, stride 32) + relu + key projection + clip + log2e
// Unchanged compute; writes scores transposed to [t][b][16].
// ---------------------------------------------------------------------------
#define TTA 256
__global__ void __launch_bounds__(128)
conv_scores_kernel(const float* __restrict__ x,
                   const float* __restrict__ conv_w,
                   const float* __restrict__ conv_b,
                   const float* __restrict__ keys)
{
    __shared__ float sx[TTA * WIN + HIST];
    __shared__ float sw[DIMS * HIST];
    __shared__ float sk[DIMS * NP];
    __shared__ float sb[DIMS];

    const int b = blockIdx.y;
    const int tile = blockIdx.x;
    const int tid = threadIdx.x;

    const long base = (long)tile * TTA * WIN - (HIST - 1);
    const float* xb = x + (size_t)b * LL;

    for (int i = tid; i < TTA * WIN + HIST; i += 128) {
        long g = base + i;
        sx[i] = (g >= 0 && g < LL) ? xb[g] : 0.f;
    }
    for (int i = tid; i < DIMS * HIST; i += 128) sw[i] = conv_w[i];
    for (int i = tid; i < DIMS * NP; i += 128)   sk[i] = keys[i];
    if (tid < DIMS) sb[tid] = conv_b[tid];
    __syncthreads();

    float acca[DIMS], accb[DIMS];
#pragma unroll
    for (int d = 0; d < DIMS; d++) { acca[d] = 0.f; accb[d] = 0.f; }

    const int ta = tid;
    const int tb = tid + 128;

    for (int h = 0; h < HIST; h++) {
        const int hp = (h + tid) & 63;
        const float xa = sx[ta * WIN + hp];
        const float xv = sx[tb * WIN + hp];
#pragma unroll
        for (int d = 0; d < DIMS; d++) {
            const float wv = sw[d * HIST + hp];
            acca[d] = fmaf(xa, wv, acca[d]);
            accb[d] = fmaf(xv, wv, accb[d]);
        }
    }

    const float L2E = 1.4426950408889634f;
#pragma unroll
    for (int s = 0; s < 2; s++) {
        const int gt = tile * TTA + tid + s * 128;
        float sc[NP];
#pragma unroll
        for (int p = 0; p < NP; p++) sc[p] = 0.f;
#pragma unroll
        for (int d = 0; d < DIMS; d++) {
            const float vd = fmaxf((s == 0 ? acca[d] : accb[d]) + sb[d], 0.f);
#pragma unroll
            for (int p = 0; p < NP; p++)
                sc[p] = fmaf(vd, sk[d * NP + p], sc[p]);
        }
        // transposed store: [t][b][16]
        float4* dst = (float4*)(g_scores + ((size_t)gt * BB + b) * NP);
#pragma unroll
        for (int q = 0; q < 4; q++) {
            float4 v;
            v.x = fminf(fmaxf(sc[q * 4 + 0], 0.f), 6.f) * L2E;
            v.y = fminf(fmaxf(sc[q * 4 + 1], 0.f), 6.f) * L2E;
            v.z = fminf(fmaxf(sc[q * 4 + 2], 0.f), 6.f) * L2E;
            v.w = fminf(fmaxf(sc[q * 4 + 3], 0.f), 6.f) * L2E;
            dst[q] = v;
        }
    }
}

// ---------------------------------------------------------------------------
// Kernel B: shfl-free chunked scan. One lane = one full 16-pattern chain.
// 8192 chains = 128 b x 64 segs; 32 chains/warp; 256 blocks x 32 threads.
// Per-step chain: z=fma(pp,-L2E,qmb) -> ex2 x16 -> treesum -> rcp -> pp.
// A-update and qmb(next) run off-chain. The -1/16 re-centering is dropped
// (uniform shift in A is softmax-invariant; log2 drift <= 29 per segment,
// safely inside fp32 range). Scores prefetched 4 steps ahead (ring qc[4]).
// ---------------------------------------------------------------------------
struct ScanState {
    float  A[NP];
    float  pp[NP];
    float  qmb[NP];
    float4 qc[4][4];
};

template<bool OUT>
__device__ __forceinline__ void scan_step(int k, int t, int b, ScanState& S,
                                          const float4* __restrict__ sp,
                                          const float* s0, const float* s1,
                                          float2* __restrict__ prm)
{
    const float L2E = 1.4426950408889634f;
    float e[NP];
#pragma unroll
    for (int i = 0; i < NP; i++)
        e[i] = ex2f(fmaf(S.pp[i], -L2E, S.qmb[i]));

    // prefetch q for step t+4 into slot k (slot k was consumed at step t-1)
    const size_t pbase = ((size_t)(t + 4) * BB + (size_t)b) * 4;
    float4 v0 = sp[pbase + 0], v1 = sp[pbase + 1],
           v2 = sp[pbase + 2], v3 = sp[pbase + 3];

#pragma unroll
    for (int i = 0; i < NP; i++)
        S.A[i] = fmaf(S.pp[i], L2E, S.A[i]);

    float ss = ((((e[0] + e[1]) + (e[2] + e[3])) + ((e[4] + e[5]) + (e[6] + e[7])))
             + (((e[8] + e[9]) + (e[10] + e[11])) + ((e[12] + e[13]) + (e[14] + e[15]))));
    float r = rcpf(ss);

    float d0, d1;
    if (OUT) {
        float a0 = 0.f, a1 = 0.f, b0 = 0.f, b1 = 0.f;
#pragma unroll
        for (int i = 0; i < NP; i += 2) {
            a0 = fmaf(e[i],     s0[i],     a0);
            b0 = fmaf(e[i + 1], s0[i + 1], b0);
            a1 = fmaf(e[i],     s1[i],     a1);
            b1 = fmaf(e[i + 1], s1[i + 1], b1);
        }
        d0 = a0 + b0; d1 = a1 + b1;
    }

#pragma unroll
    for (int i = 0; i < NP; i++) S.pp[i] = e[i] * r;

    S.qc[k][0] = v0; S.qc[k][1] = v1; S.qc[k][2] = v2; S.qc[k][3] = v3;

    // qmb for step t+1 from slot (k+1)&3 (holds q_{t+1}) and updated A
    const int kn = (k + 1) & 3;
#pragma unroll
    for (int j = 0; j < 4; j++) {
        const float4 n = S.qc[kn][j];
        S.qmb[j * 4 + 0] = n.x - S.A[j * 4 + 0];
        S.qmb[j * 4 + 1] = n.y - S.A[j * 4 + 1];
        S.qmb[j * 4 + 2] = n.z - S.A[j * 4 + 2];
        S.qmb[j * 4 + 3] = n.w - S.A[j * 4 + 3];
    }

    if (OUT) prm[(size_t)t * BB + b] = make_float2(d0 * r, d1 * r);
}

__global__ void __launch_bounds__(32)
scan_kernel(const float* __restrict__ avg0, const float* __restrict__ shapes)
{
    const int lane = threadIdx.x;
    const int seg  = blockIdx.x >> 2;              // 64 segments
    const int b    = (blockIdx.x & 3) * 32 + lane; // 128 batches

    const int s_start = seg * SEGC;
    const int t0 = (s_start >= SEGW) ? (s_start - SEGW) : 0;

    const float L2E = 1.4426950408889634f;
    const float4* sp = (const float4*)g_scores;
    float2* prm = g_params;

    ScanState S;
#pragma unroll
    for (int i = 0; i < NP; i++) {
        S.A[i]  = avg0[b * NP + i] * L2E;
        S.pp[i] = 0.f;
    }
#pragma unroll
    for (int k = 0; k < 4; k++) {
        const size_t base = ((size_t)(t0 + k) * BB + (size_t)b) * 4;
        S.qc[k][0] = sp[base + 0]; S.qc[k][1] = sp[base + 1];
        S.qc[k][2] = sp[base + 2]; S.qc[k][3] = sp[base + 3];
    }
#pragma unroll
    for (int j = 0; j < 4; j++) {
        const float4 n = S.qc[0][j];
        S.qmb[j * 4 + 0] = n.x - S.A[j * 4 + 0];
        S.qmb[j * 4 + 1] = n.y - S.A[j * 4 + 1];
        S.qmb[j * 4 + 2] = n.z - S.A[j * 4 + 2];
        S.qmb[j * 4 + 3] = n.w - S.A[j * 4 + 3];
    }

    int t = t0;
    for (; t < s_start; t += 4) {
        scan_step<false>(0, t + 0, b, S, sp, nullptr, nullptr, prm);
        scan_step<false>(1, t + 1, b, S, sp, nullptr, nullptr, prm);
        scan_step<false>(2, t + 2, b, S, sp, nullptr, nullptr, prm);
        scan_step<false>(3, t + 3, b, S, sp, nullptr, nullptr, prm);
    }

    float s0[NP], s1[NP];
#pragma unroll
    for (int i = 0; i < NP; i++) { s0[i] = shapes[i * 2]; s1[i] = shapes[i * 2 + 1]; }

    const int s_end = s_start + SEGC;
    for (; t < s_end; t += 4) {
        scan_step<true>(0, t + 0, b, S, sp, s0, s1, prm);
        scan_step<true>(1, t + 1, b, S, sp, s0, s1, prm);
        scan_step<true>(2, t + 2, b, S, sp, s0, s1, prm);
        scan_step<true>(3, t + 3, b, S, sp, s0, s1, prm);
    }
}

// ---------------------------------------------------------------------------
// Kernel C: epilogue — out = relu(offset + noise*std - x). Memory-bound.
// params layout [t][b].
// ---------------------------------------------------------------------------
__global__ void __launch_bounds__(256)
epilogue_kernel(const float* __restrict__ x,
                const float* __restrict__ noise,
                float* __restrict__ out)
{
    const int b  = blockIdx.y;
    const int l4 = blockIdx.x * 256 + threadIdx.x;
    const int t  = (l4 * 4) >> 5;

    const float2 pr = g_params[(size_t)t * BB + b];
    const float4 xv = ((const float4*)(x     + (size_t)b * LL))[l4];
    const float4 nv = ((const float4*)(noise + (size_t)b * LL))[l4];

    float4 o;
    o.x = fmaxf(fmaf(nv.x, pr.y, pr.x) - xv.x, 0.f);
    o.y = fmaxf(fmaf(nv.y, pr.y, pr.x) - xv.y, 0.f);
    o.z = fmaxf(fmaf(nv.z, pr.y, pr.x) - xv.z, 0.f);
    o.w = fmaxf(fmaf(nv.w, pr.y, pr.x) - xv.w, 0.f);
    ((float4*)out)[(size_t)b * (LL / 4) + l4] = o;
}

// ---------------------------------------------------------------------------
extern "C" void kernel_launch(void* const* d_in, const int* in_sizes, int n_in,
                              void* d_out, int out_size)
{
    const float* x      = (const float*)d_in[0];
    const float* avg    = (const float*)d_in[1];
    const float* noise  = (const float*)d_in[2];
    const float* conv_w = (const float*)d_in[3];
    const float* conv_b = (const float*)d_in[4];
    const float* keys   = (const float*)d_in[5];
    const float* shapes = (const float*)d_in[6];
    float* out = (float*)d_out;

    conv_scores_kernel<<<dim3(TT / TTA, BB), 128>>>(x, conv_w, conv_b, keys);
    scan_kernel<<<NSEG * 4, 32>>>(avg, shapes);
    epilogue_kernel<<<dim3(LL / 1024, BB), 256>>>(x, noise, out);
}

// round 6
// speedup vs baseline: 5.5980x; 1.2520x over previous
#include <cuda_runtime.h>

#define BB   128
#define LL   131072
#define TT   4096
#define HIST 64
#define WIN  32
#define DIMS 32
#define NP   16

#define SEGC   32             // output steps per segment
#define SEGW   128            // warmup steps
#define NSEG   (TT / SEGC)    // 128

typedef unsigned long long u64;

// Scores [t][b][16]; padded for scan prefetch overrun (4*BB*NP + slack).
__device__ float  g_scores[(size_t)TT * BB * NP + 16384];
// params [t][b]
__device__ float2 g_params[(size_t)TT * BB];

__device__ __forceinline__ float ex2f(float x) {
    float r; asm("ex2.approx.f32 %0, %1;" : "=f"(r) : "f"(x)); return r;
}
__device__ __forceinline__ float rcpf(float x) {
    float r; asm("rcp.approx.f32 %0, %1;" : "=f"(r) : "f"(x)); return r;
}
__device__ __forceinline__ u64 pack2(float lo, float hi) {
    u64 r; asm("mov.b64 %0, {%1, %2};" : "=l"(r) : "f"(lo), "f"(hi)); return r;
}
__device__ __forceinline__ void unpack2(u64 v, float& lo, float& hi) {
    asm("mov.b64 {%0, %1}, %2;" : "=f"(lo), "=f"(hi) : "l"(v));
}
__device__ __forceinline__ u64 ffma2(u64 a, u64 b, u64 c) {
    u64 d; asm("fma.rn.f32x2 %0, %1, %2, %3;" : "=l"(d) : "l"(a), "l"(b), "l"(c));
    return d;
}

// ---------------------------------------------------------------------------
// Kernel A: conv + relu + key projection, FFMA2 (f32x2) formulation.
// Block 128 thr = 4 warps; tile 256 t x 32 d per block, one b per blockIdx.y.
// Lane: dg = lane>>3 (d-group, 8-way broadcast for w), tl = lane&7.
// Thread tile: t = warp*64 + tl + 8*tt (tt=0..7), d = dg*8 + [0..8).
// acc packed over d-pairs: acc[tt][k] = (d=dg*8+2k, d+1), bias-initialized.
// x transposed in smem: sxT[a][c] = xpad[tile*8192 + c*32 + a], xpad = x shifted 63.
// Tap h: x = sxT[h&31][t + (h>>5)] (scalar, dup), w = sw2[h][d..d+8) (LDS.128 bcast).
// ---------------------------------------------------------------------------
#define TTA 256
#define SXT_STRIDE 258        // 257 cols needed, even stride
#define SPJ_STRIDE 34         // [t][d] pad; even for 8B-aligned u64 stores

__global__ void __launch_bounds__(128, 1)
conv_scores_kernel(const float* __restrict__ x,
                   const float* __restrict__ conv_w,
                   const float* __restrict__ conv_b,
                   const float* __restrict__ keys)
{
    __shared__ __align__(16) float sbuf[TTA * SPJ_STRIDE]; // 8704 fl; holds sxT then proj
    __shared__ __align__(16) float sw2[HIST * DIMS];       // [h][d]
    __shared__ __align__(16) float skb[DIMS * NP];         // [d][p]
    __shared__ __align__(16) float sb[DIMS];

    const int b    = blockIdx.y;
    const int tile = blockIdx.x;
    const int tid  = threadIdx.x;
    const int wrp  = tid >> 5;
    const int lane = tid & 31;
    const int dg   = lane >> 3;
    const int tl   = lane & 7;

    // ---- stage x transposed: sxT[a][c], u = tile*8192 + c*32 + a, g = u-63
    {
        const long ubase = (long)tile * (TTA * WIN);
        const float* xb = x + (size_t)b * LL;
        for (int i = tid; i < 257 * 32; i += 128) {
            const int a = i & 31, c = i >> 5;
            const long g = ubase + (long)c * 32 + a - 63;
            sbuf[a * SXT_STRIDE + c] = (g >= 0 && g < LL) ? xb[g] : 0.f;
        }
        for (int i = tid; i < HIST * DIMS; i += 128) {
            const int d = i & 31, h = i >> 5;
            sw2[h * DIMS + d] = conv_w[d * HIST + h];
        }
        for (int i = tid; i < DIMS * NP; i += 128) skb[i] = keys[i];
        if (tid < DIMS) sb[tid] = conv_b[tid];
    }
    __syncthreads();

    const int dbase = dg * 8;
    const int tbase = wrp * 64 + tl;   // + 8*tt

    // acc[tt][k]: f32x2 over (d=dbase+2k, d+1), init with bias
    u64 acc[8][4];
    {
        const float2* bp = (const float2*)&sb[dbase];
#pragma unroll
        for (int k = 0; k < 4; k++) {
            const float2 bv = bp[k];
            const u64 bi = pack2(bv.x, bv.y);
#pragma unroll
            for (int tt = 0; tt < 8; tt++) acc[tt][k] = bi;
        }
    }

#pragma unroll 1
    for (int half = 0; half < 2; half++) {       // h in [0,32) then [32,64)
        const int cofs = tbase + half;           // c = t + (h>>5)
#pragma unroll 4
        for (int hh = 0; hh < 32; hh++) {
            const int h = half * 32 + hh;
            const ulonglong2* wp = (const ulonglong2*)&sw2[h * DIMS + dbase];
            const ulonglong2 wa = wp[0], wb = wp[1];
            const float* xrow = &sbuf[hh * SXT_STRIDE + cofs];
            u64 xd[8];
#pragma unroll
            for (int tt = 0; tt < 8; tt++) {
                const float xv = xrow[8 * tt];
                xd[tt] = pack2(xv, xv);
            }
#pragma unroll
            for (int tt = 0; tt < 8; tt++) {
                acc[tt][0] = ffma2(xd[tt], wa.x, acc[tt][0]);
                acc[tt][1] = ffma2(xd[tt], wa.y, acc[tt][1]);
                acc[tt][2] = ffma2(xd[tt], wb.x, acc[tt][2]);
                acc[tt][3] = ffma2(xd[tt], wb.y, acc[tt][3]);
            }
        }
    }

    // ---- dump conv result (pre-relu) to sproj[t][d] (reusing sbuf)
    __syncthreads();   // all x reads done before overwrite
    {
        u64* sp64 = (u64*)sbuf;
#pragma unroll
        for (int tt = 0; tt < 8; tt++) {
            const int t = tbase + 8 * tt;
#pragma unroll
            for (int k = 0; k < 4; k++)
                sp64[(t * SPJ_STRIDE + dbase) / 2 + k] = acc[tt][k];
        }
    }
    __syncwarp();      // warp w reads only t in [w*64, w*64+64) = its own writes

    // ---- projection: tid handles t_a = 2*tid, t_b = 2*tid+1
    {
        const int t_a = 2 * tid;
        const int t_b = 2 * tid + 1;
        u64 sa[8], sbv[8];
#pragma unroll
        for (int j = 0; j < 8; j++) { sa[j] = 0ull; sbv[j] = 0ull; }

#pragma unroll 4
        for (int d = 0; d < DIMS; d++) {
            const ulonglong2* kp = (const ulonglong2*)&skb[d * NP];
            const ulonglong2 k0 = kp[0], k1 = kp[1], k2 = kp[2], k3 = kp[3];
            const float oa = fmaxf(sbuf[t_a * SPJ_STRIDE + d], 0.f);
            const float ob = fmaxf(sbuf[t_b * SPJ_STRIDE + d], 0.f);
            const u64 oa2 = pack2(oa, oa);
            const u64 ob2 = pack2(ob, ob);
            sa[0] = ffma2(oa2, k0.x, sa[0]);  sbv[0] = ffma2(ob2, k0.x, sbv[0]);
            sa[1] = ffma2(oa2, k0.y, sa[1]);  sbv[1] = ffma2(ob2, k0.y, sbv[1]);
            sa[2] = ffma2(oa2, k1.x, sa[2]);  sbv[2] = ffma2(ob2, k1.x, sbv[2]);
            sa[3] = ffma2(oa2, k1.y, sa[3]);  sbv[3] = ffma2(ob2, k1.y, sbv[3]);
            sa[4] = ffma2(oa2, k2.x, sa[4]);  sbv[4] = ffma2(ob2, k2.x, sbv[4]);
            sa[5] = ffma2(oa2, k2.y, sa[5]);  sbv[5] = ffma2(ob2, k2.y, sbv[5]);
            sa[6] = ffma2(oa2, k3.x, sa[6]);  sbv[6] = ffma2(ob2, k3.x, sbv[6]);
            sa[7] = ffma2(oa2, k3.y, sa[7]);  sbv[7] = ffma2(ob2, k3.y, sbv[7]);
        }

        const float L2E = 1.4426950408889634f;
#pragma unroll
        for (int s = 0; s < 2; s++) {
            const int t = (s == 0) ? t_a : t_b;
            const u64* sc = (s == 0) ? sa : sbv;
            const int gt = tile * TTA + t;
            float4* dst = (float4*)(g_scores + ((size_t)gt * BB + b) * NP);
#pragma unroll
            for (int q = 0; q < 4; q++) {
                float p0, p1, p2, p3;
                unpack2(sc[q * 2 + 0], p0, p1);
                unpack2(sc[q * 2 + 1], p2, p3);
                float4 v;
                v.x = fminf(fmaxf(p0, 0.f), 6.f) * L2E;
                v.y = fminf(fmaxf(p1, 0.f), 6.f) * L2E;
                v.z = fminf(fmaxf(p2, 0.f), 6.f) * L2E;
                v.w = fminf(fmaxf(p3, 0.f), 6.f) * L2E;
                dst[q] = v;
            }
        }
    }
}

// ---------------------------------------------------------------------------
// Kernel B: shfl-free chunked scan (SEGW=128, SEGC=32; 512 warps).
// ---------------------------------------------------------------------------
struct ScanState {
    float  A[NP];
    float  pp[NP];
    float  qmb[NP];
    float4 qc[4][4];
};

template<bool OUT>
__device__ __forceinline__ void scan_step(int k, int t, int b, ScanState& S,
                                          const float4* __restrict__ sp,
                                          const float* s0, const float* s1,
                                          float2* __restrict__ prm)
{
    const float L2E = 1.4426950408889634f;
    float e[NP];
#pragma unroll
    for (int i = 0; i < NP; i++)
        e[i] = ex2f(fmaf(S.pp[i], -L2E, S.qmb[i]));

    const size_t pbase = ((size_t)(t + 4) * BB + (size_t)b) * 4;
    float4 v0 = sp[pbase + 0], v1 = sp[pbase + 1],
           v2 = sp[pbase + 2], v3 = sp[pbase + 3];

#pragma unroll
    for (int i = 0; i < NP; i++)
        S.A[i] = fmaf(S.pp[i], L2E, S.A[i]);

    float ss = ((((e[0] + e[1]) + (e[2] + e[3])) + ((e[4] + e[5]) + (e[6] + e[7])))
             + (((e[8] + e[9]) + (e[10] + e[11])) + ((e[12] + e[13]) + (e[14] + e[15]))));
    float r = rcpf(ss);

    float d0, d1;
    if (OUT) {
        float a0 = 0.f, a1 = 0.f, b0 = 0.f, b1 = 0.f;
#pragma unroll
        for (int i = 0; i < NP; i += 2) {
            a0 = fmaf(e[i],     s0[i],     a0);
            b0 = fmaf(e[i + 1], s0[i + 1], b0);
            a1 = fmaf(e[i],     s1[i],     a1);
            b1 = fmaf(e[i + 1], s1[i + 1], b1);
        }
        d0 = a0 + b0; d1 = a1 + b1;
    }

#pragma unroll
    for (int i = 0; i < NP; i++) S.pp[i] = e[i] * r;

    S.qc[k][0] = v0; S.qc[k][1] = v1; S.qc[k][2] = v2; S.qc[k][3] = v3;

    const int kn = (k + 1) & 3;
#pragma unroll
    for (int j = 0; j < 4; j++) {
        const float4 n = S.qc[kn][j];
        S.qmb[j * 4 + 0] = n.x - S.A[j * 4 + 0];
        S.qmb[j * 4 + 1] = n.y - S.A[j * 4 + 1];
        S.qmb[j * 4 + 2] = n.z - S.A[j * 4 + 2];
        S.qmb[j * 4 + 3] = n.w - S.A[j * 4 + 3];
    }

    if (OUT) prm[(size_t)t * BB + b] = make_float2(d0 * r, d1 * r);
}

__global__ void __launch_bounds__(32)
scan_kernel(const float* __restrict__ avg0, const float* __restrict__ shapes)
{
    const int lane = threadIdx.x;
    const int seg  = blockIdx.x >> 2;
    const int b    = (blockIdx.x & 3) * 32 + lane;

    const int s_start = seg * SEGC;
    const int t0 = (s_start >= SEGW) ? (s_start - SEGW) : 0;

    const float L2E = 1.4426950408889634f;
    const float4* sp = (const float4*)g_scores;
    float2* prm = g_params;

    ScanState S;
#pragma unroll
    for (int i = 0; i < NP; i++) {
        S.A[i]  = avg0[b * NP + i] * L2E;
        S.pp[i] = 0.f;
    }
#pragma unroll
    for (int k = 0; k < 4; k++) {
        const size_t base = ((size_t)(t0 + k) * BB + (size_t)b) * 4;
        S.qc[k][0] = sp[base + 0]; S.qc[k][1] = sp[base + 1];
        S.qc[k][2] = sp[base + 2]; S.qc[k][3] = sp[base + 3];
    }
#pragma unroll
    for (int j = 0; j < 4; j++) {
        const float4 n = S.qc[0][j];
        S.qmb[j * 4 + 0] = n.x - S.A[j * 4 + 0];
        S.qmb[j * 4 + 1] = n.y - S.A[j * 4 + 1];
        S.qmb[j * 4 + 2] = n.z - S.A[j * 4 + 2];
        S.qmb[j * 4 + 3] = n.w - S.A[j * 4 + 3];
    }

    int t = t0;
    for (; t < s_start; t += 4) {
        scan_step<false>(0, t + 0, b, S, sp, nullptr, nullptr, prm);
        scan_step<false>(1, t + 1, b, S, sp, nullptr, nullptr, prm);
        scan_step<false>(2, t + 2, b, S, sp, nullptr, nullptr, prm);
        scan_step<false>(3, t + 3, b, S, sp, nullptr, nullptr, prm);
    }

    float s0[NP], s1[NP];
#pragma unroll
    for (int i = 0; i < NP; i++) { s0[i] = shapes[i * 2]; s1[i] = shapes[i * 2 + 1]; }

    const int s_end = s_start + SEGC;
    for (; t < s_end; t += 4) {
        scan_step<true>(0, t + 0, b, S, sp, s0, s1, prm);
        scan_step<true>(1, t + 1, b, S, sp, s0, s1, prm);
        scan_step<true>(2, t + 2, b, S, sp, s0, s1, prm);
        scan_step<true>(3, t + 3, b, S, sp, s0, s1, prm);
    }
}

// ---------------------------------------------------------------------------
// Kernel C: epilogue — out = relu(offset + noise*std - x). Memory-bound.
// ---------------------------------------------------------------------------
__global__ void __launch_bounds__(256)
epilogue_kernel(const float* __restrict__ x,
                const float* __restrict__ noise,
                float* __restrict__ out)
{
    const int b  = blockIdx.y;
    const int l4 = blockIdx.x * 256 + threadIdx.x;
    const int t  = (l4 * 4) >> 5;

    const float2 pr = g_params[(size_t)t * BB + b];
    const float4 xv = ((const float4*)(x     + (size_t)b * LL))[l4];
    const float4 nv = ((const float4*)(noise + (size_t)b * LL))[l4];

    float4 o;
    o.x = fmaxf(fmaf(nv.x, pr.y, pr.x) - xv.x, 0.f);
    o.y = fmaxf(fmaf(nv.y, pr.y, pr.x) - xv.y, 0.f);
    o.z = fmaxf(fmaf(nv.z, pr.y, pr.x) - xv.z, 0.f);
    o.w = fmaxf(fmaf(nv.w, pr.y, pr.x) - xv.w, 0.f);
    ((float4*)out)[(size_t)b * (LL / 4) + l4] = o;
}

// ---------------------------------------------------------------------------
extern "C" void kernel_launch(void* const* d_in, const int* in_sizes, int n_in,
                              void* d_out, int out_size)
{
    const float* x      = (const float*)d_in[0];
    const float* avg    = (const float*)d_in[1];
    const float* noise  = (const float*)d_in[2];
    const float* conv_w = (const float*)d_in[3];
    const float* conv_b = (const float*)d_in[4];
    const float* keys   = (const float*)d_in[5];
    const float* shapes = (const float*)d_in[6];
    float* out = (float*)d_out;

    conv_scores_kernel<<<dim3(TT / TTA, BB), 128>>>(x, conv_w, conv_b, keys);
    scan_kernel<<<NSEG * 4, 32>>>(avg, shapes);
    epilogue_kernel<<<dim3(LL / 1024, BB), 256>>>(x, noise, out);
}

// round 7
// speedup vs baseline: 5.9431x; 1.0617x over previous
#include <cuda_runtime.h>

#define BB   128
#define LL   131072
#define TT   4096
#define HIST 64
#define WIN  32
#define DIMS 32
#define NP   16

#define SEGC   32             // output steps per segment
#define SEGW   128            // warmup steps
#define NSEG   (TT / SEGC)    // 128

typedef unsigned long long u64;

// Scores [t][b][16]; padded for scan prefetch overrun (4*BB*NP + slack).
__device__ float  g_scores[(size_t)TT * BB * NP + 16384];
// params [t][b]
__device__ float2 g_params[(size_t)TT * BB];

__device__ __forceinline__ float ex2f(float x) {
    float r; asm("ex2.approx.f32 %0, %1;" : "=f"(r) : "f"(x)); return r;
}
__device__ __forceinline__ float rcpf(float x) {
    float r; asm("rcp.approx.f32 %0, %1;" : "=f"(r) : "f"(x)); return r;
}
__device__ __forceinline__ u64 pack2(float lo, float hi) {
    u64 r; asm("mov.b64 %0, {%1, %2};" : "=l"(r) : "f"(lo), "f"(hi)); return r;
}
__device__ __forceinline__ void unpack2(u64 v, float& lo, float& hi) {
    asm("mov.b64 {%0, %1}, %2;" : "=f"(lo), "=f"(hi) : "l"(v));
}
__device__ __forceinline__ u64 ffma2(u64 a, u64 b, u64 c) {
    u64 d; asm("fma.rn.f32x2 %0, %1, %2, %3;" : "=l"(d) : "l"(a), "l"(b), "l"(c));
    return d;
}

// ---------------------------------------------------------------------------
// Kernel A: conv + relu + key projection, FFMA2, 256 threads/block.
// Tile 256 t x 32 d per block, one b per blockIdx.y; 8 warps.
// Lane: dg = lane>>3 (w broadcast group), tl = lane&7.
// Thread conv tile: t = wrp*32 + tl + 8*tt (tt=0..3), d = dg*8 + [0..8).
// Same 45KB smem as before but 2x warps -> occupancy 22.7% -> ~62%.
// ---------------------------------------------------------------------------
#define TTA 256
#define SXT_STRIDE 258        // 257 cols needed, even stride
#define SPJ_STRIDE 34         // [t][d] pad; even for 8B-aligned u64 stores

__global__ void __launch_bounds__(256)
conv_scores_kernel(const float* __restrict__ x,
                   const float* __restrict__ conv_w,
                   const float* __restrict__ conv_b,
                   const float* __restrict__ keys)
{
    __shared__ __align__(16) float sbuf[TTA * SPJ_STRIDE]; // 8704 fl; sxT then proj
    __shared__ __align__(16) float sw2[HIST * DIMS];       // [h][d]
    __shared__ __align__(16) float skb[DIMS * NP];         // [d][p]
    __shared__ __align__(16) float sb[DIMS];

    const int b    = blockIdx.y;
    const int tile = blockIdx.x;
    const int tid  = threadIdx.x;
    const int wrp  = tid >> 5;
    const int lane = tid & 31;
    const int dg   = lane >> 3;
    const int tl   = lane & 7;

    // ---- stage x transposed: sxT[a][c], u = tile*8192 + c*32 + a, g = u-63
    {
        const long ubase = (long)tile * (TTA * WIN);
        const float* xb = x + (size_t)b * LL;
        for (int i = tid; i < 257 * 32; i += 256) {
            const int a = i & 31, c = i >> 5;
            const long g = ubase + (long)c * 32 + a - 63;
            sbuf[a * SXT_STRIDE + c] = (g >= 0 && g < LL) ? xb[g] : 0.f;
        }
        for (int i = tid; i < HIST * DIMS; i += 256) {
            const int d = i & 31, h = i >> 5;
            sw2[h * DIMS + d] = conv_w[d * HIST + h];
        }
        for (int i = tid; i < DIMS * NP; i += 256) skb[i] = keys[i];
        if (tid < DIMS) sb[tid] = conv_b[tid];
    }
    __syncthreads();

    const int dbase = dg * 8;
    const int tbase = wrp * 32 + tl;   // + 8*tt, tt=0..3

    // acc[tt][k]: f32x2 over (d=dbase+2k, d+1), init with bias
    u64 acc[4][4];
    {
        const float2* bp = (const float2*)&sb[dbase];
#pragma unroll
        for (int k = 0; k < 4; k++) {
            const float2 bv = bp[k];
            const u64 bi = pack2(bv.x, bv.y);
#pragma unroll
            for (int tt = 0; tt < 4; tt++) acc[tt][k] = bi;
        }
    }

#pragma unroll 1
    for (int half = 0; half < 2; half++) {       // h in [0,32) then [32,64)
        const int cofs = tbase + half;           // c = t + (h>>5)
#pragma unroll 4
        for (int hh = 0; hh < 32; hh++) {
            const int h = half * 32 + hh;
            const ulonglong2* wp = (const ulonglong2*)&sw2[h * DIMS + dbase];
            const ulonglong2 wa = wp[0], wb = wp[1];
            const float* xrow = &sbuf[hh * SXT_STRIDE + cofs];
            u64 xd[4];
#pragma unroll
            for (int tt = 0; tt < 4; tt++) {
                const float xv = xrow[8 * tt];
                xd[tt] = pack2(xv, xv);
            }
#pragma unroll
            for (int tt = 0; tt < 4; tt++) {
                acc[tt][0] = ffma2(xd[tt], wa.x, acc[tt][0]);
                acc[tt][1] = ffma2(xd[tt], wa.y, acc[tt][1]);
                acc[tt][2] = ffma2(xd[tt], wb.x, acc[tt][2]);
                acc[tt][3] = ffma2(xd[tt], wb.y, acc[tt][3]);
            }
        }
    }

    // ---- dump conv result (pre-relu) to sproj[t][d] (reusing sbuf)
    __syncthreads();   // all x reads done before overwrite
    {
        u64* sp64 = (u64*)sbuf;
#pragma unroll
        for (int tt = 0; tt < 4; tt++) {
            const int t = tbase + 8 * tt;
#pragma unroll
            for (int k = 0; k < 4; k++)
                sp64[(t * SPJ_STRIDE + dbase) / 2 + k] = acc[tt][k];
        }
    }
    __syncwarp();      // warp w reads only t in [w*32, w*32+32) = its own writes

    // ---- projection: thread handles t = tid (warp w covers its own t range)
    {
        const int t = tid;
        u64 sa[8];
#pragma unroll
        for (int j = 0; j < 8; j++) sa[j] = 0ull;

#pragma unroll 4
        for (int d = 0; d < DIMS; d++) {
            const ulonglong2* kp = (const ulonglong2*)&skb[d * NP];
            const ulonglong2 k0 = kp[0], k1 = kp[1], k2 = kp[2], k3 = kp[3];
            const float oa = fmaxf(sbuf[t * SPJ_STRIDE + d], 0.f);
            const u64 oa2 = pack2(oa, oa);
            sa[0] = ffma2(oa2, k0.x, sa[0]);
            sa[1] = ffma2(oa2, k0.y, sa[1]);
            sa[2] = ffma2(oa2, k1.x, sa[2]);
            sa[3] = ffma2(oa2, k1.y, sa[3]);
            sa[4] = ffma2(oa2, k2.x, sa[4]);
            sa[5] = ffma2(oa2, k2.y, sa[5]);
            sa[6] = ffma2(oa2, k3.x, sa[6]);
            sa[7] = ffma2(oa2, k3.y, sa[7]);
        }

        const float L2E = 1.4426950408889634f;
        const int gt = tile * TTA + t;
        float4* dst = (float4*)(g_scores + ((size_t)gt * BB + b) * NP);
#pragma unroll
        for (int q = 0; q < 4; q++) {
            float p0, p1, p2, p3;
            unpack2(sa[q * 2 + 0], p0, p1);
            unpack2(sa[q * 2 + 1], p2, p3);
            float4 v;
            v.x = fminf(fmaxf(p0, 0.f), 6.f) * L2E;
            v.y = fminf(fmaxf(p1, 0.f), 6.f) * L2E;
            v.z = fminf(fmaxf(p2, 0.f), 6.f) * L2E;
            v.w = fminf(fmaxf(p3, 0.f), 6.f) * L2E;
            dst[q] = v;
        }
    }
}

// ---------------------------------------------------------------------------
// Kernel B: shfl-free chunked scan (SEGW=128, SEGC=32; 512 warps).
// ---------------------------------------------------------------------------
struct ScanState {
    float  A[NP];
    float  pp[NP];
    float  qmb[NP];
    float4 qc[4][4];
};

template<bool OUT>
__device__ __forceinline__ void scan_step(int k, int t, int b, ScanState& S,
                                          const float4* __restrict__ sp,
                                          const float* s0, const float* s1,
                                          float2* __restrict__ prm)
{
    const float L2E = 1.4426950408889634f;
    float e[NP];
#pragma unroll
    for (int i = 0; i < NP; i++)
        e[i] = ex2f(fmaf(S.pp[i], -L2E, S.qmb[i]));

    const size_t pbase = ((size_t)(t + 4) * BB + (size_t)b) * 4;
    float4 v0 = sp[pbase + 0], v1 = sp[pbase + 1],
           v2 = sp[pbase + 2], v3 = sp[pbase + 3];

#pragma unroll
    for (int i = 0; i < NP; i++)
        S.A[i] = fmaf(S.pp[i], L2E, S.A[i]);

    float ss = ((((e[0] + e[1]) + (e[2] + e[3])) + ((e[4] + e[5]) + (e[6] + e[7])))
             + (((e[8] + e[9]) + (e[10] + e[11])) + ((e[12] + e[13]) + (e[14] + e[15]))));
    float r = rcpf(ss);

    float d0, d1;
    if (OUT) {
        float a0 = 0.f, a1 = 0.f, b0 = 0.f, b1 = 0.f;
#pragma unroll
        for (int i = 0; i < NP; i += 2) {
            a0 = fmaf(e[i],     s0[i],     a0);
            b0 = fmaf(e[i + 1], s0[i + 1], b0);
            a1 = fmaf(e[i],     s1[i],     a1);
            b1 = fmaf(e[i + 1], s1[i + 1], b1);
        }
        d0 = a0 + b0; d1 = a1 + b1;
    }

#pragma unroll
    for (int i = 0; i < NP; i++) S.pp[i] = e[i] * r;

    S.qc[k][0] = v0; S.qc[k][1] = v1; S.qc[k][2] = v2; S.qc[k][3] = v3;

    const int kn = (k + 1) & 3;
#pragma unroll
    for (int j = 0; j < 4; j++) {
        const float4 n = S.qc[kn][j];
        S.qmb[j * 4 + 0] = n.x - S.A[j * 4 + 0];
        S.qmb[j * 4 + 1] = n.y - S.A[j * 4 + 1];
        S.qmb[j * 4 + 2] = n.z - S.A[j * 4 + 2];
        S.qmb[j * 4 + 3] = n.w - S.A[j * 4 + 3];
    }

    if (OUT) prm[(size_t)t * BB + b] = make_float2(d0 * r, d1 * r);
}

__global__ void __launch_bounds__(32)
scan_kernel(const float* __restrict__ avg0, const float* __restrict__ shapes)
{
    const int lane = threadIdx.x;
    const int seg  = blockIdx.x >> 2;
    const int b    = (blockIdx.x & 3) * 32 + lane;

    const int s_start = seg * SEGC;
    const int t0 = (s_start >= SEGW) ? (s_start - SEGW) : 0;

    const float L2E = 1.4426950408889634f;
    const float4* sp = (const float4*)g_scores;
    float2* prm = g_params;

    ScanState S;
#pragma unroll
    for (int i = 0; i < NP; i++) {
        S.A[i]  = avg0[b * NP + i] * L2E;
        S.pp[i] = 0.f;
    }
#pragma unroll
    for (int k = 0; k < 4; k++) {
        const size_t base = ((size_t)(t0 + k) * BB + (size_t)b) * 4;
        S.qc[k][0] = sp[base + 0]; S.qc[k][1] = sp[base + 1];
        S.qc[k][2] = sp[base + 2]; S.qc[k][3] = sp[base + 3];
    }
#pragma unroll
    for (int j = 0; j < 4; j++) {
        const float4 n = S.qc[0][j];
        S.qmb[j * 4 + 0] = n.x - S.A[j * 4 + 0];
        S.qmb[j * 4 + 1] = n.y - S.A[j * 4 + 1];
        S.qmb[j * 4 + 2] = n.z - S.A[j * 4 + 2];
        S.qmb[j * 4 + 3] = n.w - S.A[j * 4 + 3];
    }

    int t = t0;
    for (; t < s_start; t += 4) {
        scan_step<false>(0, t + 0, b, S, sp, nullptr, nullptr, prm);
        scan_step<false>(1, t + 1, b, S, sp, nullptr, nullptr, prm);
        scan_step<false>(2, t + 2, b, S, sp, nullptr, nullptr, prm);
        scan_step<false>(3, t + 3, b, S, sp, nullptr, nullptr, prm);
    }

    float s0[NP], s1[NP];
#pragma unroll
    for (int i = 0; i < NP; i++) { s0[i] = shapes[i * 2]; s1[i] = shapes[i * 2 + 1]; }

    const int s_end = s_start + SEGC;
    for (; t < s_end; t += 4) {
        scan_step<true>(0, t + 0, b, S, sp, s0, s1, prm);
        scan_step<true>(1, t + 1, b, S, sp, s0, s1, prm);
        scan_step<true>(2, t + 2, b, S, sp, s0, s1, prm);
        scan_step<true>(3, t + 3, b, S, sp, s0, s1, prm);
    }
}

// ---------------------------------------------------------------------------
// Kernel C: epilogue — out = relu(offset + noise*std - x). Memory-bound.
// ---------------------------------------------------------------------------
__global__ void __launch_bounds__(256)
epilogue_kernel(const float* __restrict__ x,
                const float* __restrict__ noise,
                float* __restrict__ out)
{
    const int b  = blockIdx.y;
    const int l4 = blockIdx.x * 256 + threadIdx.x;
    const int t  = (l4 * 4) >> 5;

    const float2 pr = g_params[(size_t)t * BB + b];
    const float4 xv = ((const float4*)(x     + (size_t)b * LL))[l4];
    const float4 nv = ((const float4*)(noise + (size_t)b * LL))[l4];

    float4 o;
    o.x = fmaxf(fmaf(nv.x, pr.y, pr.x) - xv.x, 0.f);
    o.y = fmaxf(fmaf(nv.y, pr.y, pr.x) - xv.y, 0.f);
    o.z = fmaxf(fmaf(nv.z, pr.y, pr.x) - xv.z, 0.f);
    o.w = fmaxf(fmaf(nv.w, pr.y, pr.x) - xv.w, 0.f);
    ((float4*)out)[(size_t)b * (LL / 4) + l4] = o;
}

// ---------------------------------------------------------------------------
extern "C" void kernel_launch(void* const* d_in, const int* in_sizes, int n_in,
                              void* d_out, int out_size)
{
    const float* x      = (const float*)d_in[0];
    const float* avg    = (const float*)d_in[1];
    const float* noise  = (const float*)d_in[2];
    const float* conv_w = (const float*)d_in[3];
    const float* conv_b = (const float*)d_in[4];
    const float* keys   = (const float*)d_in[5];
    const float* shapes = (const float*)d_in[6];
    float* out = (float*)d_out;

    conv_scores_kernel<<<dim3(TT / TTA, BB), 256>>>(x, conv_w, conv_b, keys);
    scan_kernel<<<NSEG * 4, 32>>>(avg, shapes);
    epilogue_kernel<<<dim3(LL / 1024, BB), 256>>>(x, noise, out);
}

// round 8
// speedup vs baseline: 6.2450x; 1.0508x over previous
#include <cuda_runtime.h>

#define BB   128
#define LL   131072
#define TT   4096
#define HIST 64
#define WIN  32
#define DIMS 32
#define NP   16

#define SEGC   32             // output steps per segment
#define SEGW   96             // warmup steps (err model: ~2e-4 rel)
#define NSEG   (TT / SEGC)    // 128

typedef unsigned long long u64;

// Scores [t][b][16]; padded for scan prefetch overrun (4*BB*NP + slack).
__device__ float  g_scores[(size_t)TT * BB * NP + 16384];
// params [t][b]
__device__ float2 g_params[(size_t)TT * BB];

__device__ __forceinline__ float ex2f(float x) {
    float r; asm("ex2.approx.f32 %0, %1;" : "=f"(r) : "f"(x)); return r;
}
__device__ __forceinline__ float rcpf(float x) {
    float r; asm("rcp.approx.f32 %0, %1;" : "=f"(r) : "f"(x)); return r;
}
__device__ __forceinline__ u64 pack2(float lo, float hi) {
    u64 r; asm("mov.b64 %0, {%1, %2};" : "=l"(r) : "f"(lo), "f"(hi)); return r;
}
__device__ __forceinline__ void unpack2(u64 v, float& lo, float& hi) {
    asm("mov.b64 {%0, %1}, %2;" : "=f"(lo), "=f"(hi) : "l"(v));
}
__device__ __forceinline__ u64 ffma2(u64 a, u64 b, u64 c) {
    u64 d; asm("fma.rn.f32x2 %0, %1, %2, %3;" : "=l"(d) : "l"(a), "l"(b), "l"(c));
    return d;
}

// ---------------------------------------------------------------------------
// Kernel A: conv + relu + key projection, FFMA2, 256 threads/block.
// Tile 256 t x 32 d per block, one b per blockIdx.y; 8 warps.
// d-group is PER-WARP (dg = wid&3): every lane of a warp reads the SAME
// w addresses -> true same-address broadcast (1 wavefront per LDS.128),
// halving the L1 wavefront load vs the per-lane-dg layout.
// Warp (th=wid>>2, dg): t = th*128 + lane + 32*tt (tt=0..3), d = dg*8+[0..8).
// ---------------------------------------------------------------------------
#define TTA 256
#define SXT_STRIDE 258        // 257 cols needed, even stride
#define SPJ_STRIDE 34         // [t][d] pad; even for 8B-aligned u64 stores

__global__ void __launch_bounds__(256)
conv_scores_kernel(const float* __restrict__ x,
                   const float* __restrict__ conv_w,
                   const float* __restrict__ conv_b,
                   const float* __restrict__ keys)
{
    __shared__ __align__(16) float sbuf[TTA * SPJ_STRIDE]; // 8704 fl; sxT then proj
    __shared__ __align__(16) float sw2[HIST * DIMS];       // [h][d]
    __shared__ __align__(16) float skb[DIMS * NP];         // [d][p]
    __shared__ __align__(16) float sb[DIMS];

    const int b    = blockIdx.y;
    const int tile = blockIdx.x;
    const int tid  = threadIdx.x;
    const int wid  = tid >> 5;
    const int lane = tid & 31;
    const int dg   = wid & 3;    // per-WARP d-group
    const int th   = wid >> 2;   // t-half (0: t<128, 1: t>=128)

    // ---- stage x transposed: sxT[a][c], u = tile*8192 + c*32 + a, g = u-63
    {
        const long ubase = (long)tile * (TTA * WIN);
        const float* xb = x + (size_t)b * LL;
        for (int i = tid; i < 257 * 32; i += 256) {
            const int a = i & 31, c = i >> 5;
            const long g = ubase + (long)c * 32 + a - 63;
            sbuf[a * SXT_STRIDE + c] = (g >= 0 && g < LL) ? xb[g] : 0.f;
        }
        for (int i = tid; i < HIST * DIMS; i += 256) {
            const int d = i & 31, h = i >> 5;
            sw2[h * DIMS + d] = conv_w[d * HIST + h];
        }
        for (int i = tid; i < DIMS * NP; i += 256) skb[i] = keys[i];
        if (tid < DIMS) sb[tid] = conv_b[tid];
    }
    __syncthreads();

    const int dbase = dg * 8;
    const int tbase = th * 128 + lane;   // + 32*tt, tt=0..3

    // acc[tt][k]: f32x2 over (d=dbase+2k, d+1), init with bias
    u64 acc[4][4];
    {
        const float2* bp = (const float2*)&sb[dbase];
#pragma unroll
        for (int k = 0; k < 4; k++) {
            const float2 bv = bp[k];
            const u64 bi = pack2(bv.x, bv.y);
#pragma unroll
            for (int tt = 0; tt < 4; tt++) acc[tt][k] = bi;
        }
    }

#pragma unroll 1
    for (int half = 0; half < 2; half++) {       // h in [0,32) then [32,64)
        const int cofs = tbase + half;           // c = t + (h>>5)
#pragma unroll 4
        for (int hh = 0; hh < 32; hh++) {
            const int h = half * 32 + hh;
            // uniform across warp -> same-address broadcast, 1 wf per LDS.128
            const ulonglong2* wp = (const ulonglong2*)&sw2[h * DIMS + dbase];
            const ulonglong2 wa = wp[0], wb = wp[1];
            const float* xrow = &sbuf[hh * SXT_STRIDE + cofs];
            u64 xd[4];
#pragma unroll
            for (int tt = 0; tt < 4; tt++) {
                const float xv = xrow[32 * tt];   // lanes consecutive -> 1 wf
                xd[tt] = pack2(xv, xv);
            }
#pragma unroll
            for (int tt = 0; tt < 4; tt++) {
                acc[tt][0] = ffma2(xd[tt], wa.x, acc[tt][0]);
                acc[tt][1] = ffma2(xd[tt], wa.y, acc[tt][1]);
                acc[tt][2] = ffma2(xd[tt], wb.x, acc[tt][2]);
                acc[tt][3] = ffma2(xd[tt], wb.y, acc[tt][3]);
            }
        }
    }

    // ---- dump conv result (pre-relu) to sproj[t][d] (reusing sbuf)
    __syncthreads();   // all x reads done before overwrite
    {
        u64* sp64 = (u64*)sbuf;
#pragma unroll
        for (int tt = 0; tt < 4; tt++) {
            const int t = tbase + 32 * tt;
#pragma unroll
            for (int k = 0; k < 4; k++)
                sp64[(t * SPJ_STRIDE + dbase) / 2 + k] = acc[tt][k];
        }
    }
    __syncthreads();   // row t now assembled from 4 different warps

    // ---- projection: thread handles t = tid
    {
        const int t = tid;
        u64 sa[8];
#pragma unroll
        for (int j = 0; j < 8; j++) sa[j] = 0ull;

#pragma unroll 4
        for (int d = 0; d < DIMS; d++) {
            // uniform across warp -> broadcast
            const ulonglong2* kp = (const ulonglong2*)&skb[d * NP];
            const ulonglong2 k0 = kp[0], k1 = kp[1], k2 = kp[2], k3 = kp[3];
            const float oa = fmaxf(sbuf[t * SPJ_STRIDE + d], 0.f);
            const u64 oa2 = pack2(oa, oa);
            sa[0] = ffma2(oa2, k0.x, sa[0]);
            sa[1] = ffma2(oa2, k0.y, sa[1]);
            sa[2] = ffma2(oa2, k1.x, sa[2]);
            sa[3] = ffma2(oa2, k1.y, sa[3]);
            sa[4] = ffma2(oa2, k2.x, sa[4]);
            sa[5] = ffma2(oa2, k2.y, sa[5]);
            sa[6] = ffma2(oa2, k3.x, sa[6]);
            sa[7] = ffma2(oa2, k3.y, sa[7]);
        }

        const float L2E = 1.4426950408889634f;
        const int gt = tile * TTA + t;
        float4* dst = (float4*)(g_scores + ((size_t)gt * BB + b) * NP);
#pragma unroll
        for (int q = 0; q < 4; q++) {
            float p0, p1, p2, p3;
            unpack2(sa[q * 2 + 0], p0, p1);
            unpack2(sa[q * 2 + 1], p2, p3);
            float4 v;
            v.x = fminf(fmaxf(p0, 0.f), 6.f) * L2E;
            v.y = fminf(fmaxf(p1, 0.f), 6.f) * L2E;
            v.z = fminf(fmaxf(p2, 0.f), 6.f) * L2E;
            v.w = fminf(fmaxf(p3, 0.f), 6.f) * L2E;
            dst[q] = v;
        }
    }
}

// ---------------------------------------------------------------------------
// Kernel B: shfl-free chunked scan (SEGW=96, SEGC=32; 512 warps).
// ---------------------------------------------------------------------------
struct ScanState {
    float  A[NP];
    float  pp[NP];
    float  qmb[NP];
    float4 qc[4][4];
};

template<bool OUT>
__device__ __forceinline__ void scan_step(int k, int t, int b, ScanState& S,
                                          const float4* __restrict__ sp,
                                          const float* s0, const float* s1,
                                          float2* __restrict__ prm)
{
    const float L2E = 1.4426950408889634f;
    float e[NP];
#pragma unroll
    for (int i = 0; i < NP; i++)
        e[i] = ex2f(fmaf(S.pp[i], -L2E, S.qmb[i]));

    const size_t pbase = ((size_t)(t + 4) * BB + (size_t)b) * 4;
    float4 v0 = sp[pbase + 0], v1 = sp[pbase + 1],
           v2 = sp[pbase + 2], v3 = sp[pbase + 3];

#pragma unroll
    for (int i = 0; i < NP; i++)
        S.A[i] = fmaf(S.pp[i], L2E, S.A[i]);

    float ss = ((((e[0] + e[1]) + (e[2] + e[3])) + ((e[4] + e[5]) + (e[6] + e[7])))
             + (((e[8] + e[9]) + (e[10] + e[11])) + ((e[12] + e[13]) + (e[14] + e[15]))));
    float r = rcpf(ss);

    float d0, d1;
    if (OUT) {
        float a0 = 0.f, a1 = 0.f, b0 = 0.f, b1 = 0.f;
#pragma unroll
        for (int i = 0; i < NP; i += 2) {
            a0 = fmaf(e[i],     s0[i],     a0);
            b0 = fmaf(e[i + 1], s0[i + 1], b0);
            a1 = fmaf(e[i],     s1[i],     a1);
            b1 = fmaf(e[i + 1], s1[i + 1], b1);
        }
        d0 = a0 + b0; d1 = a1 + b1;
    }

#pragma unroll
    for (int i = 0; i < NP; i++) S.pp[i] = e[i] * r;

    S.qc[k][0] = v0; S.qc[k][1] = v1; S.qc[k][2] = v2; S.qc[k][3] = v3;

    const int kn = (k + 1) & 3;
#pragma unroll
    for (int j = 0; j < 4; j++) {
        const float4 n = S.qc[kn][j];
        S.qmb[j * 4 + 0] = n.x - S.A[j * 4 + 0];
        S.qmb[j * 4 + 1] = n.y - S.A[j * 4 + 1];
        S.qmb[j * 4 + 2] = n.z - S.A[j * 4 + 2];
        S.qmb[j * 4 + 3] = n.w - S.A[j * 4 + 3];
    }

    if (OUT) prm[(size_t)t * BB + b] = make_float2(d0 * r, d1 * r);
}

__global__ void __launch_bounds__(32)
scan_kernel(const float* __restrict__ avg0, const float* __restrict__ shapes)
{
    const int lane = threadIdx.x;
    const int seg  = blockIdx.x >> 2;
    const int b    = (blockIdx.x & 3) * 32 + lane;

    const int s_start = seg * SEGC;
    const int t0 = (s_start >= SEGW) ? (s_start - SEGW) : 0;

    const float L2E = 1.4426950408889634f;
    const float4* sp = (const float4*)g_scores;
    float2* prm = g_params;

    ScanState S;
#pragma unroll
    for (int i = 0; i < NP; i++) {
        S.A[i]  = avg0[b * NP + i] * L2E;
        S.pp[i] = 0.f;
    }
#pragma unroll
    for (int k = 0; k < 4; k++) {
        const size_t base = ((size_t)(t0 + k) * BB + (size_t)b) * 4;
        S.qc[k][0] = sp[base + 0]; S.qc[k][1] = sp[base + 1];
        S.qc[k][2] = sp[base + 2]; S.qc[k][3] = sp[base + 3];
    }
#pragma unroll
    for (int j = 0; j < 4; j++) {
        const float4 n = S.qc[0][j];
        S.qmb[j * 4 + 0] = n.x - S.A[j * 4 + 0];
        S.qmb[j * 4 + 1] = n.y - S.A[j * 4 + 1];
        S.qmb[j * 4 + 2] = n.z - S.A[j * 4 + 2];
        S.qmb[j * 4 + 3] = n.w - S.A[j * 4 + 3];
    }

    int t = t0;
    for (; t < s_start; t += 4) {
        scan_step<false>(0, t + 0, b, S, sp, nullptr, nullptr, prm);
        scan_step<false>(1, t + 1, b, S, sp, nullptr, nullptr, prm);
        scan_step<false>(2, t + 2, b, S, sp, nullptr, nullptr, prm);
        scan_step<false>(3, t + 3, b, S, sp, nullptr, nullptr, prm);
    }

    float s0[NP], s1[NP];
#pragma unroll
    for (int i = 0; i < NP; i++) { s0[i] = shapes[i * 2]; s1[i] = shapes[i * 2 + 1]; }

    const int s_end = s_start + SEGC;
    for (; t < s_end; t += 4) {
        scan_step<true>(0, t + 0, b, S, sp, s0, s1, prm);
        scan_step<true>(1, t + 1, b, S, sp, s0, s1, prm);
        scan_step<true>(2, t + 2, b, S, sp, s0, s1, prm);
        scan_step<true>(3, t + 3, b, S, sp, s0, s1, prm);
    }
}

// ---------------------------------------------------------------------------
// Kernel C: epilogue — out = relu(offset + noise*std - x). Memory-bound.
// ---------------------------------------------------------------------------
__global__ void __launch_bounds__(256)
epilogue_kernel(const float* __restrict__ x,
                const float* __restrict__ noise,
                float* __restrict__ out)
{
    const int b  = blockIdx.y;
    const int l4 = blockIdx.x * 256 + threadIdx.x;
    const int t  = (l4 * 4) >> 5;

    const float2 pr = g_params[(size_t)t * BB + b];
    const float4 xv = ((const float4*)(x     + (size_t)b * LL))[l4];
    const float4 nv = ((const float4*)(noise + (size_t)b * LL))[l4];

    float4 o;
    o.x = fmaxf(fmaf(nv.x, pr.y, pr.x) - xv.x, 0.f);
    o.y = fmaxf(fmaf(nv.y, pr.y, pr.x) - xv.y, 0.f);
    o.z = fmaxf(fmaf(nv.z, pr.y, pr.x) - xv.z, 0.f);
    o.w = fmaxf(fmaf(nv.w, pr.y, pr.x) - xv.w, 0.f);
    ((float4*)out)[(size_t)b * (LL / 4) + l4] = o;
}

// ---------------------------------------------------------------------------
extern "C" void kernel_launch(void* const* d_in, const int* in_sizes, int n_in,
                              void* d_out, int out_size)
{
    const float* x      = (const float*)d_in[0];
    const float* avg    = (const float*)d_in[1];
    const float* noise  = (const float*)d_in[2];
    const float* conv_w = (const float*)d_in[3];
    const float* conv_b = (const float*)d_in[4];
    const float* keys   = (const float*)d_in[5];
    const float* shapes = (const float*)d_in[6];
    float* out = (float*)d_out;

    conv_scores_kernel<<<dim3(TT / TTA, BB), 256>>>(x, conv_w, conv_b, keys);
    scan_kernel<<<NSEG * 4, 32>>>(avg, shapes);
    epilogue_kernel<<<dim3(LL / 1024, BB), 256>>>(x, noise, out);
}

// round 9
// speedup vs baseline: 6.5132x; 1.0430x over previous
#include <cuda_runtime.h>

#define BB   128
#define LL   131072
#define TT   4096
#define HIST 64
#define WIN  32
#define DIMS 32
#define NP   16

#define SEGC   32             // output steps per segment
#define SEGW   96             // warmup steps (rel_err ~3.7e-4, 2.7x margin)
#define NSEG   (TT / SEGC)    // 128

typedef unsigned long long u64;

// Scores [t][b][16]; padded for scan prefetch overrun (4*BB*NP + slack).
__device__ float  g_scores[(size_t)TT * BB * NP + 16384];
// params [t][b]
__device__ float2 g_params[(size_t)TT * BB];

__device__ __forceinline__ float ex2f(float x) {
    float r; asm("ex2.approx.f32 %0, %1;" : "=f"(r) : "f"(x)); return r;
}
__device__ __forceinline__ float rcpf(float x) {
    float r; asm("rcp.approx.f32 %0, %1;" : "=f"(r) : "f"(x)); return r;
}
__device__ __forceinline__ u64 pack2(float lo, float hi) {
    u64 r; asm("mov.b64 %0, {%1, %2};" : "=l"(r) : "f"(lo), "f"(hi)); return r;
}
__device__ __forceinline__ void unpack2(u64 v, float& lo, float& hi) {
    asm("mov.b64 {%0, %1}, %2;" : "=f"(lo), "=f"(hi) : "l"(v));
}
__device__ __forceinline__ u64 ffma2(u64 a, u64 b, u64 c) {
    u64 d; asm("fma.rn.f32x2 %0, %1, %2, %3;" : "=l"(d) : "l"(a), "l"(b), "l"(c));
    return d;
}

// ---------------------------------------------------------------------------
// Kernel A: conv + relu + key projection, FFMA2, 256 threads/block.
// Conv core identical to R8. Projection register-blocked: 128 threads,
// each computing a 4t x 8p tile (t = q + 64*i), so k-rows are loaded once
// per d per thread and reused across 4 t -> proj smem reads drop ~3x.
// ---------------------------------------------------------------------------
#define TTA 256
#define SXT_STRIDE 258        // 257 cols needed, even stride
#define SPJ_STRIDE 34         // [t][d] pad; even for 8B-aligned u64 stores

__global__ void __launch_bounds__(256)
conv_scores_kernel(const float* __restrict__ x,
                   const float* __restrict__ conv_w,
                   const float* __restrict__ conv_b,
                   const float* __restrict__ keys)
{
    __shared__ __align__(16) float sbuf[TTA * SPJ_STRIDE]; // 8704 fl; sxT then proj
    __shared__ __align__(16) float sw2[HIST * DIMS];       // [h][d]
    __shared__ __align__(16) float skb[DIMS * NP];         // [d][p]
    __shared__ __align__(16) float sb[DIMS];

    const int b    = blockIdx.y;
    const int tile = blockIdx.x;
    const int tid  = threadIdx.x;
    const int wid  = tid >> 5;
    const int lane = tid & 31;
    const int dg   = wid & 3;    // per-warp d-group
    const int th   = wid >> 2;   // t-half

    // ---- stage x transposed: sxT[a][c], u = tile*8192 + c*32 + a, g = u-63
    {
        const long ubase = (long)tile * (TTA * WIN);
        const float* xb = x + (size_t)b * LL;
        for (int i = tid; i < 257 * 32; i += 256) {
            const int a = i & 31, c = i >> 5;
            const long g = ubase + (long)c * 32 + a - 63;
            sbuf[a * SXT_STRIDE + c] = (g >= 0 && g < LL) ? xb[g] : 0.f;
        }
        for (int i = tid; i < HIST * DIMS; i += 256) {
            const int d = i & 31, h = i >> 5;
            sw2[h * DIMS + d] = conv_w[d * HIST + h];
        }
        for (int i = tid; i < DIMS * NP; i += 256) skb[i] = keys[i];
        if (tid < DIMS) sb[tid] = conv_b[tid];
    }
    __syncthreads();

    const int dbase = dg * 8;
    const int tbase = th * 128 + lane;   // + 32*tt, tt=0..3

    // acc[tt][k]: f32x2 over (d=dbase+2k, d+1), init with bias
    u64 acc[4][4];
    {
        const float2* bp = (const float2*)&sb[dbase];
#pragma unroll
        for (int k = 0; k < 4; k++) {
            const float2 bv = bp[k];
            const u64 bi = pack2(bv.x, bv.y);
#pragma unroll
            for (int tt = 0; tt < 4; tt++) acc[tt][k] = bi;
        }
    }

#pragma unroll 1
    for (int half = 0; half < 2; half++) {       // h in [0,32) then [32,64)
        const int cofs = tbase + half;           // c = t + (h>>5)
#pragma unroll 4
        for (int hh = 0; hh < 32; hh++) {
            const int h = half * 32 + hh;
            const ulonglong2* wp = (const ulonglong2*)&sw2[h * DIMS + dbase];
            const ulonglong2 wa = wp[0], wb = wp[1];
            const float* xrow = &sbuf[hh * SXT_STRIDE + cofs];
            u64 xd[4];
#pragma unroll
            for (int tt = 0; tt < 4; tt++) {
                const float xv = xrow[32 * tt];
                xd[tt] = pack2(xv, xv);
            }
#pragma unroll
            for (int tt = 0; tt < 4; tt++) {
                acc[tt][0] = ffma2(xd[tt], wa.x, acc[tt][0]);
                acc[tt][1] = ffma2(xd[tt], wa.y, acc[tt][1]);
                acc[tt][2] = ffma2(xd[tt], wb.x, acc[tt][2]);
                acc[tt][3] = ffma2(xd[tt], wb.y, acc[tt][3]);
            }
        }
    }

    // ---- dump conv result (pre-relu) to sproj[t][d] (reusing sbuf)
    __syncthreads();   // all x reads done before overwrite
    {
        u64* sp64 = (u64*)sbuf;
#pragma unroll
        for (int tt = 0; tt < 4; tt++) {
            const int t = tbase + 32 * tt;
#pragma unroll
            for (int k = 0; k < 4; k++)
                sp64[(t * SPJ_STRIDE + dbase) / 2 + k] = acc[tt][k];
        }
    }
    __syncthreads();   // row t assembled from 4 warps

    // ---- projection: 128 threads, thread = (q, ph) computes 4t x 8p tile.
    // t_i = q + 64*i  (lane-consecutive q -> conflict-free spj reads)
    if (tid < 128) {
        const int q  = tid >> 1;     // 0..63
        const int ph = tid & 1;      // p-half: p in [ph*8, ph*8+8)
        u64 pa[4][4];
#pragma unroll
        for (int i = 0; i < 4; i++)
#pragma unroll
            for (int j = 0; j < 4; j++) pa[i][j] = 0ull;

#pragma unroll 4
        for (int d = 0; d < DIMS; d++) {
            const u64* kp = (const u64*)&skb[d * NP + ph * 8];
            const u64 k0 = kp[0], k1 = kp[1], k2 = kp[2], k3 = kp[3];
#pragma unroll
            for (int i = 0; i < 4; i++) {
                const int t = q + 64 * i;
                const float oa = fmaxf(sbuf[t * SPJ_STRIDE + d], 0.f);
                const u64 o2 = pack2(oa, oa);
                pa[i][0] = ffma2(o2, k0, pa[i][0]);
                pa[i][1] = ffma2(o2, k1, pa[i][1]);
                pa[i][2] = ffma2(o2, k2, pa[i][2]);
                pa[i][3] = ffma2(o2, k3, pa[i][3]);
            }
        }

        const float L2E = 1.4426950408889634f;
#pragma unroll
        for (int i = 0; i < 4; i++) {
            const int gt = tile * TTA + q + 64 * i;
            float4* dst = (float4*)(g_scores + ((size_t)gt * BB + b) * NP + ph * 8);
#pragma unroll
            for (int v = 0; v < 2; v++) {
                float p0, p1, p2, p3;
                unpack2(pa[i][v * 2 + 0], p0, p1);
                unpack2(pa[i][v * 2 + 1], p2, p3);
                float4 o;
                o.x = fminf(fmaxf(p0, 0.f), 6.f) * L2E;
                o.y = fminf(fmaxf(p1, 0.f), 6.f) * L2E;
                o.z = fminf(fmaxf(p2, 0.f), 6.f) * L2E;
                o.w = fminf(fmaxf(p3, 0.f), 6.f) * L2E;
                dst[v] = o;
            }
        }
    }
}

// ---------------------------------------------------------------------------
// Kernel B: shfl-free chunked scan (SEGW=96, SEGC=32; 512 warps).
// ---------------------------------------------------------------------------
struct ScanState {
    float  A[NP];
    float  pp[NP];
    float  qmb[NP];
    float4 qc[4][4];
};

template<bool OUT>
__device__ __forceinline__ void scan_step(int k, int t, int b, ScanState& S,
                                          const float4* __restrict__ sp,
                                          const float* s0, const float* s1,
                                          float2* __restrict__ prm)
{
    const float L2E = 1.4426950408889634f;
    float e[NP];
#pragma unroll
    for (int i = 0; i < NP; i++)
        e[i] = ex2f(fmaf(S.pp[i], -L2E, S.qmb[i]));

    const size_t pbase = ((size_t)(t + 4) * BB + (size_t)b) * 4;
    float4 v0 = sp[pbase + 0], v1 = sp[pbase + 1],
           v2 = sp[pbase + 2], v3 = sp[pbase + 3];

#pragma unroll
    for (int i = 0; i < NP; i++)
        S.A[i] = fmaf(S.pp[i], L2E, S.A[i]);

    float ss = ((((e[0] + e[1]) + (e[2] + e[3])) + ((e[4] + e[5]) + (e[6] + e[7])))
             + (((e[8] + e[9]) + (e[10] + e[11])) + ((e[12] + e[13]) + (e[14] + e[15]))));
    float r = rcpf(ss);

    float d0, d1;
    if (OUT) {
        float a0 = 0.f, a1 = 0.f, b0 = 0.f, b1 = 0.f;
#pragma unroll
        for (int i = 0; i < NP; i += 2) {
            a0 = fmaf(e[i],     s0[i],     a0);
            b0 = fmaf(e[i + 1], s0[i + 1], b0);
            a1 = fmaf(e[i],     s1[i],     a1);
            b1 = fmaf(e[i + 1], s1[i + 1], b1);
        }
        d0 = a0 + b0; d1 = a1 + b1;
    }

#pragma unroll
    for (int i = 0; i < NP; i++) S.pp[i] = e[i] * r;

    S.qc[k][0] = v0; S.qc[k][1] = v1; S.qc[k][2] = v2; S.qc[k][3] = v3;

    const int kn = (k + 1) & 3;
#pragma unroll
    for (int j = 0; j < 4; j++) {
        const float4 n = S.qc[kn][j];
        S.qmb[j * 4 + 0] = n.x - S.A[j * 4 + 0];
        S.qmb[j * 4 + 1] = n.y - S.A[j * 4 + 1];
        S.qmb[j * 4 + 2] = n.z - S.A[j * 4 + 2];
        S.qmb[j * 4 + 3] = n.w - S.A[j * 4 + 3];
    }

    if (OUT) prm[(size_t)t * BB + b] = make_float2(d0 * r, d1 * r);
}

__global__ void __launch_bounds__(32)
scan_kernel(const float* __restrict__ avg0, const float* __restrict__ shapes)
{
    const int lane = threadIdx.x;
    const int seg  = blockIdx.x >> 2;
    const int b    = (blockIdx.x & 3) * 32 + lane;

    const int s_start = seg * SEGC;
    const int t0 = (s_start >= SEGW) ? (s_start - SEGW) : 0;

    const float L2E = 1.4426950408889634f;
    const float4* sp = (const float4*)g_scores;
    float2* prm = g_params;

    ScanState S;
#pragma unroll
    for (int i = 0; i < NP; i++) {
        S.A[i]  = avg0[b * NP + i] * L2E;
        S.pp[i] = 0.f;
    }
#pragma unroll
    for (int k = 0; k < 4; k++) {
        const size_t base = ((size_t)(t0 + k) * BB + (size_t)b) * 4;
        S.qc[k][0] = sp[base + 0]; S.qc[k][1] = sp[base + 1];
        S.qc[k][2] = sp[base + 2]; S.qc[k][3] = sp[base + 3];
    }
#pragma unroll
    for (int j = 0; j < 4; j++) {
        const float4 n = S.qc[0][j];
        S.qmb[j * 4 + 0] = n.x - S.A[j * 4 + 0];
        S.qmb[j * 4 + 1] = n.y - S.A[j * 4 + 1];
        S.qmb[j * 4 + 2] = n.z - S.A[j * 4 + 2];
        S.qmb[j * 4 + 3] = n.w - S.A[j * 4 + 3];
    }

    int t = t0;
    for (; t < s_start; t += 4) {
        scan_step<false>(0, t + 0, b, S, sp, nullptr, nullptr, prm);
        scan_step<false>(1, t + 1, b, S, sp, nullptr, nullptr, prm);
        scan_step<false>(2, t + 2, b, S, sp, nullptr, nullptr, prm);
        scan_step<false>(3, t + 3, b, S, sp, nullptr, nullptr, prm);
    }

    float s0[NP], s1[NP];
#pragma unroll
    for (int i = 0; i < NP; i++) { s0[i] = shapes[i * 2]; s1[i] = shapes[i * 2 + 1]; }

    const int s_end = s_start + SEGC;
    for (; t < s_end; t += 4) {
        scan_step<true>(0, t + 0, b, S, sp, s0, s1, prm);
        scan_step<true>(1, t + 1, b, S, sp, s0, s1, prm);
        scan_step<true>(2, t + 2, b, S, sp, s0, s1, prm);
        scan_step<true>(3, t + 3, b, S, sp, s0, s1, prm);
    }
}

// ---------------------------------------------------------------------------
// Kernel C: epilogue — out = relu(offset + noise*std - x). Memory-bound.
// ---------------------------------------------------------------------------
__global__ void __launch_bounds__(256)
epilogue_kernel(const float* __restrict__ x,
                const float* __restrict__ noise,
                float* __restrict__ out)
{
    const int b  = blockIdx.y;
    const int l4 = blockIdx.x * 256 + threadIdx.x;
    const int t  = (l4 * 4) >> 5;

    const float2 pr = g_params[(size_t)t * BB + b];
    const float4 xv = ((const float4*)(x     + (size_t)b * LL))[l4];
    const float4 nv = ((const float4*)(noise + (size_t)b * LL))[l4];

    float4 o;
    o.x = fmaxf(fmaf(nv.x, pr.y, pr.x) - xv.x, 0.f);
    o.y = fmaxf(fmaf(nv.y, pr.y, pr.x) - xv.y, 0.f);
    o.z = fmaxf(fmaf(nv.z, pr.y, pr.x) - xv.z, 0.f);
    o.w = fmaxf(fmaf(nv.w, pr.y, pr.x) - xv.w, 0.f);
    ((float4*)out)[(size_t)b * (LL / 4) + l4] = o;
}

// ---------------------------------------------------------------------------
extern "C" void kernel_launch(void* const* d_in, const int* in_sizes, int n_in,
                              void* d_out, int out_size)
{
    const float* x      = (const float*)d_in[0];
    const float* avg    = (const float*)d_in[1];
    const float* noise  = (const float*)d_in[2];
    const float* conv_w = (const float*)d_in[3];
    const float* conv_b = (const float*)d_in[4];
    const float* keys   = (const float*)d_in[5];
    const float* shapes = (const float*)d_in[6];
    float* out = (float*)d_out;

    conv_scores_kernel<<<dim3(TT / TTA, BB), 256>>>(x, conv_w, conv_b, keys);
    scan_kernel<<<NSEG * 4, 32>>>(avg, shapes);
    epilogue_kernel<<<dim3(LL / 1024, BB), 256>>>(x, noise, out);
}